// round 2
// baseline (speedup 1.0000x reference)
#include <cuda_runtime.h>
#include <cuda_bf16.h>
#include <cfloat>

#define LEAKF 0.2f

// ---------------- device scratch (no allocation allowed) ----------------
__device__ float g_d[4L * 4096 * 4096];   // 256 MB distance matrices
__device__ float g_cat[16384L * 512];     // x1|x2|x3|x4 concat, ld=512
__device__ float g_qp[16384L * 512];      // [q|p] packed, ld = 2*O
__device__ float g_x2[16384];
__device__ int   g_idx[16384L * 20];
__device__ float g_local[16384L * 512];
__device__ float g_emb[16384L * 1024];
__device__ float g_part[64L * 1024];
__device__ float g_glob[4L * 1024];
__device__ float g_gh[4L * 256];
__device__ float g_h1[16384L * 256];
__device__ float g_h2[16384L * 256];
__device__ float g_wp[512 * 128];         // packed [w1; w2-w1], max 2*256 x 128

__device__ __forceinline__ float lrelu(float v) { return v > 0.f ? v : LEAKF * v; }

// ---------------- 128x128 tiled fp32 GEMM using packed fma.rn.f32x2 ----------------
// Y[m][n] = sum_k X[m][k] * W[n][k]   (both row-major, arbitrary ld, batched via z)
// MODE 0: Y = acc
// MODE 1: Y = leaky(acc*s[n] + b[n])
// MODE 2: Y = x2[m] + x2[n] - 2*acc          (pairwise sq. distance; aux=x2, per-z)
// MODE 3: Y = leaky(s[n]*(acc + aux[(m>>12)*auxS + n]) + b[n])
// MODE 4: Y = acc + b[n]
template<int MODE>
__global__ __launch_bounds__(256, 2)
void gemm_k(const float* __restrict__ X, int ldx, long xbs,
            const float* __restrict__ W, int ldw, long wbs,
            float* __restrict__ Y, int ldy, long ybs,
            int M, int K, int NO,
            const float* __restrict__ sv,
            const float* __restrict__ bv,
            const float* __restrict__ aux, int auxS)
{
    __shared__ float Xs[16][132];
    __shared__ float Ws[16][132];
    int z = blockIdx.z;
    const float* Xb = X + (long)z * xbs;
    const float* Wb = W + (long)z * wbs;
    float* Yb = Y + (long)z * ybs;
    int row0 = blockIdx.y * 128;
    int col0 = blockIdx.x * 128;
    int tid = threadIdx.x;
    int tx = tid & 15, ty = tid >> 4;      // 16x16 threads, 8x8 outputs each
    int lm  = tid >> 1;                    // loader row 0..127
    int lk0 = (tid & 1) * 8;               // loader k offset 0 or 8

    // accumulators: 8 rows x 4 col-pairs, packed f32x2 (lo = even col)
    unsigned long long acc[8][4];
#pragma unroll
    for (int i = 0; i < 8; i++)
#pragma unroll
        for (int j = 0; j < 4; j++) acc[i][j] = 0ull;   // bit pattern of (0.f, 0.f)

    int gmL = row0 + lm;
    int gnL = col0 + lm;

    for (int k0 = 0; k0 < K; k0 += 16) {
#pragma unroll
        for (int j = 0; j < 8; j++) {
            int gk = k0 + lk0 + j;
            Xs[lk0 + j][lm] = (gmL < M  && gk < K) ? Xb[(long)gmL * ldx + gk] : 0.f;
            Ws[lk0 + j][lm] = (gnL < NO && gk < K) ? Wb[(long)gnL * ldw + gk] : 0.f;
        }
        __syncthreads();
#pragma unroll
        for (int kk = 0; kk < 16; kk++) {
            float a[8];
            *(float4*)&a[0] = *(const float4*)&Xs[kk][ty * 8];
            *(float4*)&a[4] = *(const float4*)&Xs[kk][ty * 8 + 4];
            ulonglong2 b01 = *(const ulonglong2*)&Ws[kk][tx * 8];       // (b0,b1),(b2,b3)
            ulonglong2 b23 = *(const ulonglong2*)&Ws[kk][tx * 8 + 4];   // (b4,b5),(b6,b7)
            unsigned long long bb0 = b01.x, bb1 = b01.y, bb2 = b23.x, bb3 = b23.y;
#pragma unroll
            for (int i = 0; i < 8; i++) {
                unsigned long long aa;
                asm("mov.b64 %0, {%1, %1};" : "=l"(aa) : "f"(a[i]));
                asm("fma.rn.f32x2 %0, %1, %2, %0;" : "+l"(acc[i][0]) : "l"(aa), "l"(bb0));
                asm("fma.rn.f32x2 %0, %1, %2, %0;" : "+l"(acc[i][1]) : "l"(aa), "l"(bb1));
                asm("fma.rn.f32x2 %0, %1, %2, %0;" : "+l"(acc[i][2]) : "l"(aa), "l"(bb2));
                asm("fma.rn.f32x2 %0, %1, %2, %0;" : "+l"(acc[i][3]) : "l"(aa), "l"(bb3));
            }
        }
        __syncthreads();
    }

#pragma unroll
    for (int i = 0; i < 8; i++) {
        int gm = row0 + ty * 8 + i;
        if (gm >= M) continue;
#pragma unroll
        for (int j = 0; j < 4; j++) {
            union { unsigned long long u; float f[2]; } cv;
            cv.u = acc[i][j];
#pragma unroll
            for (int h = 0; h < 2; h++) {
                int gn = col0 + tx * 8 + 2 * j + h;
                if (gn >= NO) continue;
                float v = cv.f[h];
                if (MODE == 1) v = lrelu(v * sv[gn] + bv[gn]);
                else if (MODE == 2) {
                    const float* x2 = aux + (long)z * auxS;
                    v = x2[gm] + x2[gn] - 2.f * v;
                } else if (MODE == 3) {
                    int b = gm >> 12;
                    v = lrelu(sv[gn] * (v + aux[b * auxS + gn]) + bv[gn]);
                } else if (MODE == 4) v = v + bv[gn];
                Yb[(long)gm * ldy + gn] = v;
            }
        }
    }
}

// ---------------- squared norms (warp per row) ----------------
__global__ void sqnorm_k(const float* __restrict__ X, int ldx, int C, float* __restrict__ x2)
{
    int warp = (blockIdx.x * blockDim.x + threadIdx.x) >> 5;
    int lane = threadIdx.x & 31;
    if (warp >= 16384) return;
    const float* xr = X + (long)warp * ldx;
    float s = 0.f;
    for (int c = lane; c < C; c += 32) { float v = xr[c]; s = fmaf(v, v, s); }
#pragma unroll
    for (int off = 16; off; off >>= 1) s += __shfl_down_sync(0xffffffffu, s, off);
    if (lane == 0) x2[warp] = s;
}

// ---------------- top-20 smallest (u64-packed keys, warp-shuffle reduce) ----------------
__global__ __launch_bounds__(128) void topk_k(const float* __restrict__ D, int* __restrict__ idx)
{
    __shared__ float vals[4096];
    __shared__ unsigned long long wmin[4];
    long r = blockIdx.x;
    const float* drow = D + r * 4096;
    int tid = threadIdx.x;
    int lane = tid & 31, warp = tid >> 5;
    for (int j = tid; j < 4096; j += 128) vals[j] = drow[j];
    __syncthreads();
    for (int t = 0; t < 20; t++) {
        unsigned long long best = ~0ull;
        for (int j = tid; j < 4096; j += 128) {
            unsigned u = __float_as_uint(vals[j]);
            u = (u & 0x80000000u) ? ~u : (u | 0x80000000u);  // order-preserving map
            unsigned long long key = ((unsigned long long)u << 32) | (unsigned)j;
            best = key < best ? key : best;
        }
#pragma unroll
        for (int off = 16; off; off >>= 1) {
            unsigned long long o = __shfl_down_sync(0xffffffffu, best, off);
            best = o < best ? o : best;
        }
        if (lane == 0) wmin[warp] = best;
        __syncthreads();
        if (tid == 0) {
            unsigned long long b = wmin[0];
            for (int w = 1; w < 4; w++) b = wmin[w] < b ? wmin[w] : b;
            int bi = (int)(b & 0xffffffffu);
            idx[r * 20 + t] = bi;
            vals[bi] = FLT_MAX;
        }
        __syncthreads();
    }
}

// ---------------- weight pack: wp[0:O][c]=w[o][c], wp[O:2O][c]=w[o][C+c]-w[o][c] ------
__global__ void wpack_k(const float* __restrict__ w, int C, int O, float* __restrict__ wp)
{
    int i = blockIdx.x * blockDim.x + threadIdx.x;
    if (i >= O * C) return;
    int o = i / C, c = i - o * C;
    float wa = w[o * 2 * C + c];
    wp[o * C + c] = wa;
    wp[(O + o) * C + c] = w[o * 2 * C + C + c] - wa;
}

// ---------------- edge gather + max + BN + leaky ----------------
__global__ void combine_k(const float* __restrict__ qp, int O,
                          const int* __restrict__ idx,
                          const float* __restrict__ sv, const float* __restrict__ bv,
                          float* __restrict__ out, int ldo)
{
    __shared__ int nb[20];
    int r = blockIdx.x;
    int base = (r >> 12) << 12;
    int tid = threadIdx.x;
    int ldq = 2 * O;
    if (tid < 20) nb[tid] = idx[(long)r * 20 + tid];
    __syncthreads();
    for (int o = tid; o < O; o += blockDim.x) {
        float m = -FLT_MAX;
#pragma unroll
        for (int kk = 0; kk < 20; kk++)
            m = fmaxf(m, qp[(long)(base + nb[kk]) * ldq + o]);
        float v = sv[o] * (m + qp[(long)r * ldq + O + o]) + bv[o];
        out[(long)r * ldo + o] = lrelu(v);
    }
}

// ---------------- global max over N (two-pass) ----------------
__global__ void gmax1_k(const float* __restrict__ emb, float* __restrict__ part)
{
    int b = blockIdx.x >> 4, sp = blockIdx.x & 15;
    int o = blockIdx.y * 256 + threadIdx.x;
    const float* e = emb + ((long)b * 4096 + (long)sp * 256) * 1024 + o;
    float m = -FLT_MAX;
    for (int n = 0; n < 256; n++) m = fmaxf(m, e[(long)n * 1024]);
    part[(long)blockIdx.x * 1024 + o] = m;
}
__global__ void gmax2_k(const float* __restrict__ part, float* __restrict__ glob)
{
    int b = blockIdx.x; int o = blockIdx.y * 256 + threadIdx.x;
    float m = -FLT_MAX;
    for (int sp = 0; sp < 16; sp++) m = fmaxf(m, part[(long)(b * 16 + sp) * 1024 + o]);
    glob[(long)b * 1024 + o] = m;
}

// ---------------- host helper ----------------
static void gemm(int mode,
                 const float* X, int ldx, long xbs,
                 const float* W, int ldw, long wbs,
                 float* Y, int ldy, long ybs,
                 int M, int K, int NO, int Z,
                 const float* sv, const float* bv,
                 const float* aux, int auxS)
{
    dim3 grid((NO + 127) / 128, (M + 127) / 128, Z);
    switch (mode) {
    case 0: gemm_k<0><<<grid, 256>>>(X, ldx, xbs, W, ldw, wbs, Y, ldy, ybs, M, K, NO, sv, bv, aux, auxS); break;
    case 1: gemm_k<1><<<grid, 256>>>(X, ldx, xbs, W, ldw, wbs, Y, ldy, ybs, M, K, NO, sv, bv, aux, auxS); break;
    case 2: gemm_k<2><<<grid, 256>>>(X, ldx, xbs, W, ldw, wbs, Y, ldy, ybs, M, K, NO, sv, bv, aux, auxS); break;
    case 3: gemm_k<3><<<grid, 256>>>(X, ldx, xbs, W, ldw, wbs, Y, ldy, ybs, M, K, NO, sv, bv, aux, auxS); break;
    case 4: gemm_k<4><<<grid, 256>>>(X, ldx, xbs, W, ldw, wbs, Y, ldy, ybs, M, K, NO, sv, bv, aux, auxS); break;
    }
}

extern "C" void kernel_launch(void* const* d_in, const int* in_sizes, int n_in,
                              void* d_out, int out_size)
{
    (void)in_sizes; (void)n_in; (void)out_size;
    const float* xyz = (const float*)d_in[0];
    const float* w1 = (const float*)d_in[2];  const float* s1 = (const float*)d_in[3];  const float* b1 = (const float*)d_in[4];
    const float* w2 = (const float*)d_in[5];  const float* s2 = (const float*)d_in[6];  const float* b2 = (const float*)d_in[7];
    const float* w3 = (const float*)d_in[8];  const float* s3 = (const float*)d_in[9];  const float* b3 = (const float*)d_in[10];
    const float* w4 = (const float*)d_in[11]; const float* s4 = (const float*)d_in[12]; const float* b4 = (const float*)d_in[13];
    const float* wf = (const float*)d_in[14]; const float* sf = (const float*)d_in[15]; const float* bf = (const float*)d_in[16];
    const float* we = (const float*)d_in[17]; const float* se = (const float*)d_in[18]; const float* be = (const float*)d_in[19];
    const float* wh1 = (const float*)d_in[20]; const float* sh1 = (const float*)d_in[21]; const float* bh1 = (const float*)d_in[22];
    const float* wh2 = (const float*)d_in[23]; const float* sh2 = (const float*)d_in[24]; const float* bh2 = (const float*)d_in[25];
    const float* wh3 = (const float*)d_in[26]; const float* bh3 = (const float*)d_in[27];
    float* out = (float*)d_out;

    float *gd, *gcat, *gqp, *gx2, *glocal, *gemb, *gpart, *gglob, *ggh, *gh1, *gh2, *gwp;
    int *gidx;
    cudaGetSymbolAddress((void**)&gd, g_d);
    cudaGetSymbolAddress((void**)&gcat, g_cat);
    cudaGetSymbolAddress((void**)&gqp, g_qp);
    cudaGetSymbolAddress((void**)&gx2, g_x2);
    cudaGetSymbolAddress((void**)&gidx, g_idx);
    cudaGetSymbolAddress((void**)&glocal, g_local);
    cudaGetSymbolAddress((void**)&gemb, g_emb);
    cudaGetSymbolAddress((void**)&gpart, g_part);
    cudaGetSymbolAddress((void**)&gglob, g_glob);
    cudaGetSymbolAddress((void**)&ggh, g_gh);
    cudaGetSymbolAddress((void**)&gh1, g_h1);
    cudaGetSymbolAddress((void**)&gh2, g_h2);
    cudaGetSymbolAddress((void**)&gwp, g_wp);

    const int B = 4, N = 4096, M = B * N;

    auto edge_layer = [&](const float* X, int ldx, int C,
                          const float* w, const float* sv, const float* bv,
                          int O, float* outCol) {
        wpack_k<<<(O * C + 255) / 256, 256>>>(w, C, O, gwp);
        sqnorm_k<<<M / 8, 256>>>(X, ldx, C, gx2);
        gemm(2, X, ldx, (long)N * ldx, X, ldx, (long)N * ldx,
             gd, N, (long)N * N, N, C, N, B, nullptr, nullptr, gx2, N);
        topk_k<<<M, 128>>>(gd, gidx);
        // [q|p] = X * [w1 ; (w2-w1)]^T  -> [M, 2O]
        gemm(0, X, ldx, 0, gwp, C, 0, gqp, 2 * O, 0, M, C, 2 * O, 1, nullptr, nullptr, nullptr, 0);
        combine_k<<<M, 128>>>(gqp, O, gidx, sv, bv, outCol, 512);
    };

    edge_layer(xyz,        3,   3,   w1, s1, b1, 64,  gcat + 0);
    edge_layer(gcat + 0,   512, 64,  w2, s2, b2, 64,  gcat + 64);
    edge_layer(gcat + 64,  512, 64,  w3, s3, b3, 128, gcat + 128);
    edge_layer(gcat + 128, 512, 128, w4, s4, b4, 256, gcat + 256);

    gemm(1, gcat, 512, 0, wf, 512, 0, glocal, 512, 0, M, 512, 512, 1, sf, bf, nullptr, 0);
    gemm(1, glocal, 512, 0, we, 512, 0, gemb, 1024, 0, M, 512, 1024, 1, se, be, nullptr, 0);
    { dim3 g1(64, 4); gmax1_k<<<g1, 256>>>(gemb, gpart); }
    { dim3 g2(4, 4);  gmax2_k<<<g2, 256>>>(gpart, gglob); }
    gemm(0, gglob, 1024, 0, wh1 + 512, 1536, 0, ggh, 256, 0, B, 1024, 256, 1, nullptr, nullptr, nullptr, 0);
    gemm(3, glocal, 512, 0, wh1, 1536, 0, gh1, 256, 0, M, 512, 256, 1, sh1, bh1, ggh, 256);
    gemm(1, gh1, 256, 0, wh2, 256, 0, gh2, 256, 0, M, 256, 256, 1, sh2, bh2, nullptr, 0);
    gemm(4, gh2, 256, 0, wh3, 256, 0, out, 50, 0, M, 256, 50, 1, nullptr, bh3, nullptr, 0);
}

// round 3
// speedup vs baseline: 1.4280x; 1.4280x over previous
#include <cuda_runtime.h>
#include <cuda_bf16.h>
#include <cfloat>

#define LEAKF 0.2f

// ---------------- device scratch (no allocation allowed) ----------------
__device__ float g_d[4L * 4096 * 4096];   // 256 MB distance matrices
__device__ float g_cat[16384L * 512];     // x1|x2|x3|x4 concat, ld=512
__device__ float g_qp[16384L * 512];      // [q|p] packed, ld = 2*O
__device__ float g_x2[16384];
__device__ int   g_idx[16384L * 20];
__device__ float g_local[16384L * 512];
__device__ float g_emb[16384L * 1024];
__device__ float g_part[64L * 1024];
__device__ float g_glob[4L * 1024];
__device__ float g_gh[4L * 256];
__device__ float g_h1[16384L * 256];
__device__ float g_h2[16384L * 256];
__device__ float g_wp[512 * 128];         // packed [w1; w2-w1], max 2*256 x 128

__device__ __forceinline__ float lrelu(float v) { return v > 0.f ? v : LEAKF * v; }

// ---------------- 64x64 tiled fp32 GEMM with fused epilogues (round-1 proven) ----
// Y[m][n] = sum_k X[m][k] * W[n][k]   (both row-major, arbitrary ld, batched via z)
// MODE 0: Y = acc
// MODE 1: Y = leaky(acc*s[n] + b[n])
// MODE 2: Y = x2[m] + x2[n] - 2*acc          (pairwise sq. distance; aux=x2, per-z)
// MODE 3: Y = leaky(s[n]*(acc + aux[(m>>12)*auxS + n]) + b[n])
// MODE 4: Y = acc + b[n]
template<int MODE>
__global__ void gemm_k(const float* __restrict__ X, int ldx, long xbs,
                       const float* __restrict__ W, int ldw, long wbs,
                       float* __restrict__ Y, int ldy, long ybs,
                       int M, int K, int NO,
                       const float* __restrict__ sv,
                       const float* __restrict__ bv,
                       const float* __restrict__ aux, int auxS)
{
    __shared__ float Xs[16][64];
    __shared__ float Ws[16][68];
    int z = blockIdx.z;
    const float* Xb = X + (long)z * xbs;
    const float* Wb = W + (long)z * wbs;
    float* Yb = Y + (long)z * ybs;
    int row0 = blockIdx.y * 64;
    int col0 = blockIdx.x * 64;
    int tid = threadIdx.x;
    int tx = tid & 15, ty = tid >> 4;
    int lm = tid >> 2;
    int lk4 = (tid & 3) * 4;

    float acc[4][4] = {};

    for (int k0 = 0; k0 < K; k0 += 16) {
#pragma unroll
        for (int j = 0; j < 4; j++) {
            int kk = lk4 + j;
            int gm = row0 + lm, gk = k0 + kk;
            Xs[kk][lm] = (gm < M && gk < K) ? Xb[(long)gm * ldx + gk] : 0.f;
        }
#pragma unroll
        for (int j = 0; j < 4; j++) {
            int kk = lk4 + j;
            int gn = col0 + lm, gk = k0 + kk;
            Ws[kk][lm] = (gn < NO && gk < K) ? Wb[(long)gn * ldw + gk] : 0.f;
        }
        __syncthreads();
#pragma unroll
        for (int kk = 0; kk < 16; kk++) {
            float a[4], b[4];
#pragma unroll
            for (int i = 0; i < 4; i++) a[i] = Xs[kk][ty * 4 + i];
#pragma unroll
            for (int j = 0; j < 4; j++) b[j] = Ws[kk][tx * 4 + j];
#pragma unroll
            for (int i = 0; i < 4; i++)
#pragma unroll
                for (int j = 0; j < 4; j++)
                    acc[i][j] = fmaf(a[i], b[j], acc[i][j]);
        }
        __syncthreads();
    }

#pragma unroll
    for (int i = 0; i < 4; i++) {
        int gm = row0 + ty * 4 + i;
        if (gm >= M) continue;
#pragma unroll
        for (int j = 0; j < 4; j++) {
            int gn = col0 + tx * 4 + j;
            if (gn >= NO) continue;
            float v = acc[i][j];
            if (MODE == 1) v = lrelu(v * sv[gn] + bv[gn]);
            else if (MODE == 2) {
                const float* x2 = aux + (long)z * auxS;
                v = x2[gm] + x2[gn] - 2.f * v;
            } else if (MODE == 3) {
                int b = gm >> 12;
                v = lrelu(sv[gn] * (v + aux[b * auxS + gn]) + bv[gn]);
            } else if (MODE == 4) v = v + bv[gn];
            Yb[(long)gm * ldy + gn] = v;
        }
    }
}

// ---------------- squared norms (warp per row) ----------------
__global__ void sqnorm_k(const float* __restrict__ X, int ldx, int C, float* __restrict__ x2)
{
    int warp = (blockIdx.x * blockDim.x + threadIdx.x) >> 5;
    int lane = threadIdx.x & 31;
    if (warp >= 16384) return;
    const float* xr = X + (long)warp * ldx;
    float s = 0.f;
    for (int c = lane; c < C; c += 32) { float v = xr[c]; s = fmaf(v, v, s); }
#pragma unroll
    for (int off = 16; off; off >>= 1) s += __shfl_down_sync(0xffffffffu, s, off);
    if (lane == 0) x2[warp] = s;
}

// ---------------- top-20 smallest via 3-level radix select ----------------
// Order-preserving key map; confirmed elements emitted per pass (output order
// is irrelevant: consumer is a max over the neighbor set). Boundary candidates
// resolved by unique packed (key, idx) iterative min.
__global__ __launch_bounds__(256) void topk_k(const float* __restrict__ D, int* __restrict__ idx)
{
    __shared__ unsigned skey[4096];
    __shared__ int hist[256];
    __shared__ int cand[2048];
    __shared__ int sb, socnt, sccnt;
    __shared__ unsigned long long wred[8];
    __shared__ unsigned long long s_last;

    long r = blockIdx.x;
    const float* drow = D + r * 4096;
    int* orow = idx + r * 20;
    int tid = threadIdx.x;
    int lane = tid & 31, warp = tid >> 5;

    for (int j = tid; j < 4096; j += 256) {
        unsigned u = __float_as_uint(drow[j]);
        skey[j] = (u & 0x80000000u) ? ~u : (u | 0x80000000u);
    }
    if (tid == 0) { socnt = 0; s_last = 0ull; }
    __syncthreads();

    unsigned prefix = 0, pmask = 0;
    int need = 20;

    for (int pass = 0; pass < 3; pass++) {
        int shift = 24 - 8 * pass;
        hist[tid] = 0;
        __syncthreads();
        for (int j = tid; j < 4096; j += 256) {
            unsigned u = skey[j];
            if ((u & pmask) == prefix) atomicAdd(&hist[(u >> shift) & 255u], 1);
        }
        __syncthreads();
        // inclusive scan over 256 bins (Hillis-Steele)
        int v = hist[tid];
#pragma unroll
        for (int off = 1; off < 256; off <<= 1) {
            int t = (tid >= off) ? hist[tid - off] : 0;
            __syncthreads();
            v += t; hist[tid] = v;
            __syncthreads();
        }
        int excl_self = tid ? hist[tid - 1] : 0;
        if (excl_self < need && hist[tid] >= need) sb = tid;
        __syncthreads();
        int b = sb;
        int excl = b ? hist[b - 1] : 0;
        // emit elements confirmed in top-20 (digit strictly below boundary bin)
        for (int j = tid; j < 4096; j += 256) {
            unsigned u = skey[j];
            if ((u & pmask) == prefix && ((u >> shift) & 255u) < (unsigned)b) {
                int p = atomicAdd(&socnt, 1);
                orow[p] = j;
            }
        }
        prefix |= (unsigned)b << shift;
        pmask |= 0xFFu << shift;
        need -= excl;
        __syncthreads();
    }

    // compact boundary-prefix candidates
    if (tid == 0) sccnt = 0;
    __syncthreads();
    for (int j = tid; j < 4096; j += 256) {
        if ((skey[j] & pmask) == prefix) {
            int p = atomicAdd(&sccnt, 1);
            if (p < 2048) cand[p] = j;
        }
    }
    __syncthreads();
    int m = sccnt;
    bool fits = (m <= 2048);
    int obase = socnt;

    for (int t = 0; t < need; t++) {
        unsigned long long last = s_last;
        unsigned long long best = ~0ull;
        if (fits) {
            for (int c = tid; c < m; c += 256) {
                int j = cand[c];
                unsigned long long key = ((unsigned long long)skey[j] << 32) | (unsigned)j;
                if (key > last && key < best) best = key;
            }
        } else {
            for (int j = tid; j < 4096; j += 256) {
                unsigned u = skey[j];
                if ((u & pmask) == prefix) {
                    unsigned long long key = ((unsigned long long)u << 32) | (unsigned)j;
                    if (key > last && key < best) best = key;
                }
            }
        }
#pragma unroll
        for (int off = 16; off; off >>= 1) {
            unsigned long long o = __shfl_down_sync(0xffffffffu, best, off);
            if (o < best) best = o;
        }
        if (lane == 0) wred[warp] = best;
        __syncthreads();
        if (tid == 0) {
            unsigned long long bb = wred[0];
#pragma unroll
            for (int w = 1; w < 8; w++) if (wred[w] < bb) bb = wred[w];
            orow[obase + t] = (int)(bb & 0xffffffffu);
            s_last = bb;
        }
        __syncthreads();
    }
}

// ---------------- weight pack: wp[0:O][c]=w[o][c], wp[O:2O][c]=w[o][C+c]-w[o][c] ------
__global__ void wpack_k(const float* __restrict__ w, int C, int O, float* __restrict__ wp)
{
    int i = blockIdx.x * blockDim.x + threadIdx.x;
    if (i >= O * C) return;
    int o = i / C, c = i - o * C;
    float wa = w[o * 2 * C + c];
    wp[o * C + c] = wa;
    wp[(O + o) * C + c] = w[o * 2 * C + C + c] - wa;
}

// ---------------- edge gather + max + BN + leaky ----------------
__global__ void combine_k(const float* __restrict__ qp, int O,
                          const int* __restrict__ idx,
                          const float* __restrict__ sv, const float* __restrict__ bv,
                          float* __restrict__ out, int ldo)
{
    __shared__ int nb[20];
    int r = blockIdx.x;
    int base = (r >> 12) << 12;
    int tid = threadIdx.x;
    int ldq = 2 * O;
    if (tid < 20) nb[tid] = idx[(long)r * 20 + tid];
    __syncthreads();
    for (int o = tid; o < O; o += blockDim.x) {
        float m = -FLT_MAX;
#pragma unroll
        for (int kk = 0; kk < 20; kk++)
            m = fmaxf(m, qp[(long)(base + nb[kk]) * ldq + o]);
        float v = sv[o] * (m + qp[(long)r * ldq + O + o]) + bv[o];
        out[(long)r * ldo + o] = lrelu(v);
    }
}

// ---------------- global max over N (two-pass) ----------------
__global__ void gmax1_k(const float* __restrict__ emb, float* __restrict__ part)
{
    int b = blockIdx.x >> 4, sp = blockIdx.x & 15;
    int o = blockIdx.y * 256 + threadIdx.x;
    const float* e = emb + ((long)b * 4096 + (long)sp * 256) * 1024 + o;
    float m = -FLT_MAX;
    for (int n = 0; n < 256; n++) m = fmaxf(m, e[(long)n * 1024]);
    part[(long)blockIdx.x * 1024 + o] = m;
}
__global__ void gmax2_k(const float* __restrict__ part, float* __restrict__ glob)
{
    int b = blockIdx.x; int o = blockIdx.y * 256 + threadIdx.x;
    float m = -FLT_MAX;
    for (int sp = 0; sp < 16; sp++) m = fmaxf(m, part[(long)(b * 16 + sp) * 1024 + o]);
    glob[(long)b * 1024 + o] = m;
}

// ---------------- host helper ----------------
static void gemm(int mode,
                 const float* X, int ldx, long xbs,
                 const float* W, int ldw, long wbs,
                 float* Y, int ldy, long ybs,
                 int M, int K, int NO, int Z,
                 const float* sv, const float* bv,
                 const float* aux, int auxS)
{
    dim3 grid((NO + 63) / 64, (M + 63) / 64, Z);
    switch (mode) {
    case 0: gemm_k<0><<<grid, 256>>>(X, ldx, xbs, W, ldw, wbs, Y, ldy, ybs, M, K, NO, sv, bv, aux, auxS); break;
    case 1: gemm_k<1><<<grid, 256>>>(X, ldx, xbs, W, ldw, wbs, Y, ldy, ybs, M, K, NO, sv, bv, aux, auxS); break;
    case 2: gemm_k<2><<<grid, 256>>>(X, ldx, xbs, W, ldw, wbs, Y, ldy, ybs, M, K, NO, sv, bv, aux, auxS); break;
    case 3: gemm_k<3><<<grid, 256>>>(X, ldx, xbs, W, ldw, wbs, Y, ldy, ybs, M, K, NO, sv, bv, aux, auxS); break;
    case 4: gemm_k<4><<<grid, 256>>>(X, ldx, xbs, W, ldw, wbs, Y, ldy, ybs, M, K, NO, sv, bv, aux, auxS); break;
    }
}

extern "C" void kernel_launch(void* const* d_in, const int* in_sizes, int n_in,
                              void* d_out, int out_size)
{
    (void)in_sizes; (void)n_in; (void)out_size;
    const float* xyz = (const float*)d_in[0];
    const float* w1 = (const float*)d_in[2];  const float* s1 = (const float*)d_in[3];  const float* b1 = (const float*)d_in[4];
    const float* w2 = (const float*)d_in[5];  const float* s2 = (const float*)d_in[6];  const float* b2 = (const float*)d_in[7];
    const float* w3 = (const float*)d_in[8];  const float* s3 = (const float*)d_in[9];  const float* b3 = (const float*)d_in[10];
    const float* w4 = (const float*)d_in[11]; const float* s4 = (const float*)d_in[12]; const float* b4 = (const float*)d_in[13];
    const float* wf = (const float*)d_in[14]; const float* sf = (const float*)d_in[15]; const float* bf = (const float*)d_in[16];
    const float* we = (const float*)d_in[17]; const float* se = (const float*)d_in[18]; const float* be = (const float*)d_in[19];
    const float* wh1 = (const float*)d_in[20]; const float* sh1 = (const float*)d_in[21]; const float* bh1 = (const float*)d_in[22];
    const float* wh2 = (const float*)d_in[23]; const float* sh2 = (const float*)d_in[24]; const float* bh2 = (const float*)d_in[25];
    const float* wh3 = (const float*)d_in[26]; const float* bh3 = (const float*)d_in[27];
    float* out = (float*)d_out;

    float *gd, *gcat, *gqp, *gx2, *glocal, *gemb, *gpart, *gglob, *ggh, *gh1, *gh2, *gwp;
    int *gidx;
    cudaGetSymbolAddress((void**)&gd, g_d);
    cudaGetSymbolAddress((void**)&gcat, g_cat);
    cudaGetSymbolAddress((void**)&gqp, g_qp);
    cudaGetSymbolAddress((void**)&gx2, g_x2);
    cudaGetSymbolAddress((void**)&gidx, g_idx);
    cudaGetSymbolAddress((void**)&glocal, g_local);
    cudaGetSymbolAddress((void**)&gemb, g_emb);
    cudaGetSymbolAddress((void**)&gpart, g_part);
    cudaGetSymbolAddress((void**)&gglob, g_glob);
    cudaGetSymbolAddress((void**)&ggh, g_gh);
    cudaGetSymbolAddress((void**)&gh1, g_h1);
    cudaGetSymbolAddress((void**)&gh2, g_h2);
    cudaGetSymbolAddress((void**)&gwp, g_wp);

    const int B = 4, N = 4096, M = B * N;

    auto edge_layer = [&](const float* X, int ldx, int C,
                          const float* w, const float* sv, const float* bv,
                          int O, float* outCol) {
        wpack_k<<<(O * C + 255) / 256, 256>>>(w, C, O, gwp);
        sqnorm_k<<<M / 8, 256>>>(X, ldx, C, gx2);
        gemm(2, X, ldx, (long)N * ldx, X, ldx, (long)N * ldx,
             gd, N, (long)N * N, N, C, N, B, nullptr, nullptr, gx2, N);
        topk_k<<<M, 256>>>(gd, gidx);
        // [q|p] = X * [w1 ; (w2-w1)]^T  -> [M, 2O]
        gemm(0, X, ldx, 0, gwp, C, 0, gqp, 2 * O, 0, M, C, 2 * O, 1, nullptr, nullptr, nullptr, 0);
        combine_k<<<M, 128>>>(gqp, O, gidx, sv, bv, outCol, 512);
    };

    edge_layer(xyz,        3,   3,   w1, s1, b1, 64,  gcat + 0);
    edge_layer(gcat + 0,   512, 64,  w2, s2, b2, 64,  gcat + 64);
    edge_layer(gcat + 64,  512, 64,  w3, s3, b3, 128, gcat + 128);
    edge_layer(gcat + 128, 512, 128, w4, s4, b4, 256, gcat + 256);

    gemm(1, gcat, 512, 0, wf, 512, 0, glocal, 512, 0, M, 512, 512, 1, sf, bf, nullptr, 0);
    gemm(1, glocal, 512, 0, we, 512, 0, gemb, 1024, 0, M, 512, 1024, 1, se, be, nullptr, 0);
    { dim3 g1(64, 4); gmax1_k<<<g1, 256>>>(gemb, gpart); }
    { dim3 g2(4, 4);  gmax2_k<<<g2, 256>>>(gpart, gglob); }
    gemm(0, gglob, 1024, 0, wh1 + 512, 1536, 0, ggh, 256, 0, B, 1024, 256, 1, nullptr, nullptr, nullptr, 0);
    gemm(3, glocal, 512, 0, wh1, 1536, 0, gh1, 256, 0, M, 512, 256, 1, sh1, bh1, ggh, 256);
    gemm(1, gh1, 256, 0, wh2, 256, 0, gh2, 256, 0, M, 256, 256, 1, sh2, bh2, nullptr, 0);
    gemm(4, gh2, 256, 0, wh3, 256, 0, out, 50, 0, M, 256, 50, 1, nullptr, bh3, nullptr, 0);
}

// round 5
// speedup vs baseline: 1.4855x; 1.0403x over previous
#include <cuda_runtime.h>
#include <cuda_bf16.h>
#include <cfloat>

#define LEAKF 0.2f

// ---------------- device scratch (no allocation allowed) ----------------
__device__ float g_d[4L * 4096 * 4096];   // 256 MB distance matrices
__device__ float g_cat[16384L * 512];     // x1|x2|x3|x4 concat, ld=512
__device__ float g_qp[16384L * 512];      // [q|p] packed, ld = 2*O
__device__ float g_x2[16384];
__device__ int   g_idx[16384L * 20];
__device__ float g_local[16384L * 512];
__device__ float g_emb[16384L * 1024];
__device__ float g_part[64L * 1024];
__device__ float g_glob[4L * 1024];
__device__ float g_gh[4L * 256];
__device__ float g_h1[16384L * 256];
__device__ float g_h2[16384L * 256];
__device__ float g_wp[512 * 128];         // packed [w1; w2-w1], max 2*256 x 128

__device__ __forceinline__ float lrelu(float v) { return v > 0.f ? v : LEAKF * v; }

__device__ __forceinline__ unsigned f2tf32(float v) {
    unsigned r;
    asm("cvt.rna.tf32.f32 %0, %1;" : "=r"(r) : "f"(v));
    return r;
}

// ---------------- 128x128 3xTF32 tensor-core GEMM with fused epilogues -------------
// Y[m][n] = sum_k X[m][k] * W[n][k]   (both row-major, arbitrary ld, batched via z)
// 3xTF32: x = hi + lo (both tf32);  x*y ~= xh*yh + xh*yl + xl*yh  -> ~fp32 precision.
// MODE 0: Y = acc
// MODE 1: Y = leaky(acc*s[n] + b[n])
// MODE 2: Y = x2[m] + x2[n] - 2*acc          (pairwise sq. distance; aux=x2, per-z)
// MODE 3: Y = leaky(s[n]*(acc + aux[(m>>12)*auxS + n]) + b[n])
// MODE 4: Y = acc + b[n]
// 8 warps: warp tile 32(m) x 64(n); mma.m16n8k8.tf32, fp32 accumulate.
#define SPAD 20
template<int MODE>
__global__ __launch_bounds__(256, 2)
void gemm_t(const float* __restrict__ X, int ldx, long xbs,
            const float* __restrict__ W, int ldw, long wbs,
            float* __restrict__ Y, int ldy, long ybs,
            int M, int K, int NO,
            const float* __restrict__ sv,
            const float* __restrict__ bv,
            const float* __restrict__ aux, int auxS)
{
    __shared__ unsigned Ah[128 * SPAD];
    __shared__ unsigned Al[128 * SPAD];
    __shared__ unsigned Bh[128 * SPAD];
    __shared__ unsigned Bl[128 * SPAD];

    int z = blockIdx.z;
    const float* Xb = X + (long)z * xbs;
    const float* Wb = W + (long)z * wbs;
    float* Yb = Y + (long)z * ybs;
    int row0 = blockIdx.y * 128;
    int col0 = blockIdx.x * 128;
    int tid = threadIdx.x;
    int lane = tid & 31, wid = tid >> 5;
    int wm = wid & 3;        // 4 m-tiles of 32
    int wn = wid >> 2;       // 2 n-tiles of 64
    int grp = lane >> 2, tig = lane & 3;

    float acc[2][8][4];
#pragma unroll
    for (int h = 0; h < 2; h++)
#pragma unroll
        for (int j = 0; j < 8; j++)
#pragma unroll
            for (int c = 0; c < 4; c++) acc[h][j][c] = 0.f;

    int nchunks = (K + 15) >> 4;
    for (int ch = 0; ch < nchunks; ch++) {
        int k0 = ch << 4;
#pragma unroll
        for (int i = 0; i < 8; i++) {
            int li = tid * 8 + i;          // 0..2047
            int rrow = li >> 4, rcol = li & 15;
            int gk = k0 + rcol;
            int gm = row0 + rrow;
            float va = (gm < M && gk < K) ? Xb[(long)gm * ldx + gk] : 0.f;
            unsigned vah = f2tf32(va);
            Ah[rrow * SPAD + rcol] = vah;
            Al[rrow * SPAD + rcol] = f2tf32(va - __uint_as_float(vah));
            int gn = col0 + rrow;
            float vb = (gn < NO && gk < K) ? Wb[(long)gn * ldw + gk] : 0.f;
            unsigned vbh = f2tf32(vb);
            Bh[rrow * SPAD + rcol] = vbh;
            Bl[rrow * SPAD + rcol] = f2tf32(vb - __uint_as_float(vbh));
        }
        __syncthreads();

#pragma unroll
        for (int ks = 0; ks < 16; ks += 8) {
            unsigned ah[2][4], al[2][4];
#pragma unroll
            for (int h = 0; h < 2; h++) {
                int mb = wm * 32 + h * 16;
                int i0 = (mb + grp) * SPAD + ks + tig;
                int i1 = (mb + grp + 8) * SPAD + ks + tig;
                ah[h][0] = Ah[i0]; ah[h][1] = Ah[i1];
                ah[h][2] = Ah[i0 + 4]; ah[h][3] = Ah[i1 + 4];
                al[h][0] = Al[i0]; al[h][1] = Al[i1];
                al[h][2] = Al[i0 + 4]; al[h][3] = Al[i1 + 4];
            }
#pragma unroll
            for (int j = 0; j < 8; j++) {
                int nb = wn * 64 + j * 8;
                int ib = (nb + grp) * SPAD + ks + tig;
                unsigned bh0 = Bh[ib], bh1 = Bh[ib + 4];
                unsigned bl0 = Bl[ib], bl1 = Bl[ib + 4];
#pragma unroll
                for (int h = 0; h < 2; h++) {
                    // lo x hi  +  hi x lo  +  hi x hi
                    asm volatile(
                        "mma.sync.aligned.m16n8k8.row.col.f32.tf32.tf32.f32 "
                        "{%0,%1,%2,%3}, {%4,%5,%6,%7}, {%8,%9}, {%0,%1,%2,%3};"
                        : "+f"(acc[h][j][0]), "+f"(acc[h][j][1]),
                          "+f"(acc[h][j][2]), "+f"(acc[h][j][3])
                        : "r"(al[h][0]), "r"(al[h][1]), "r"(al[h][2]), "r"(al[h][3]),
                          "r"(bh0), "r"(bh1));
                    asm volatile(
                        "mma.sync.aligned.m16n8k8.row.col.f32.tf32.tf32.f32 "
                        "{%0,%1,%2,%3}, {%4,%5,%6,%7}, {%8,%9}, {%0,%1,%2,%3};"
                        : "+f"(acc[h][j][0]), "+f"(acc[h][j][1]),
                          "+f"(acc[h][j][2]), "+f"(acc[h][j][3])
                        : "r"(ah[h][0]), "r"(ah[h][1]), "r"(ah[h][2]), "r"(ah[h][3]),
                          "r"(bl0), "r"(bl1));
                    asm volatile(
                        "mma.sync.aligned.m16n8k8.row.col.f32.tf32.tf32.f32 "
                        "{%0,%1,%2,%3}, {%4,%5,%6,%7}, {%8,%9}, {%0,%1,%2,%3};"
                        : "+f"(acc[h][j][0]), "+f"(acc[h][j][1]),
                          "+f"(acc[h][j][2]), "+f"(acc[h][j][3])
                        : "r"(ah[h][0]), "r"(ah[h][1]), "r"(ah[h][2]), "r"(ah[h][3]),
                          "r"(bh0), "r"(bh1));
                }
            }
        }
        __syncthreads();
    }

    // epilogue
#pragma unroll
    for (int h = 0; h < 2; h++) {
        int r0 = row0 + wm * 32 + h * 16 + grp;
#pragma unroll
        for (int j = 0; j < 8; j++) {
            int cb = col0 + wn * 64 + j * 8 + 2 * tig;
#pragma unroll
            for (int half = 0; half < 2; half++) {
                int gm = r0 + half * 8;
                if (gm >= M) continue;
#pragma unroll
                for (int cc = 0; cc < 2; cc++) {
                    int gn = cb + cc;
                    if (gn >= NO) continue;
                    float v = acc[h][j][half * 2 + cc];
                    if (MODE == 1) v = lrelu(v * sv[gn] + bv[gn]);
                    else if (MODE == 2) {
                        const float* x2 = aux + (long)z * auxS;
                        v = x2[gm] + x2[gn] - 2.f * v;
                    } else if (MODE == 3) {
                        int bb = gm >> 12;
                        v = lrelu(sv[gn] * (v + aux[bb * auxS + gn]) + bv[gn]);
                    } else if (MODE == 4) v = v + bv[gn];
                    Yb[(long)gm * ldy + gn] = v;
                }
            }
        }
    }
}

// ---------------- squared norms (warp per row) ----------------
__global__ void sqnorm_k(const float* __restrict__ X, int ldx, int C, float* __restrict__ x2)
{
    int warp = (blockIdx.x * blockDim.x + threadIdx.x) >> 5;
    int lane = threadIdx.x & 31;
    if (warp >= 16384) return;
    const float* xr = X + (long)warp * ldx;
    float s = 0.f;
    for (int c = lane; c < C; c += 32) { float v = xr[c]; s = fmaf(v, v, s); }
#pragma unroll
    for (int off = 16; off; off >>= 1) s += __shfl_down_sync(0xffffffffu, s, off);
    if (lane == 0) x2[warp] = s;
}

// ---------------- top-20 smallest via 3-level radix select ----------------
__global__ __launch_bounds__(256) void topk_k(const float* __restrict__ D, int* __restrict__ idx)
{
    __shared__ unsigned skey[4096];
    __shared__ int hist[256];
    __shared__ int cand[2048];
    __shared__ int sb, socnt, sccnt;
    __shared__ unsigned long long wred[8];
    __shared__ unsigned long long s_last;

    long r = blockIdx.x;
    const float* drow = D + r * 4096;
    int* orow = idx + r * 20;
    int tid = threadIdx.x;
    int lane = tid & 31, warp = tid >> 5;

    for (int j = tid; j < 4096; j += 256)
        skey[j] = __float_as_uint(fmaxf(drow[j], 0.f));
    if (tid == 0) { socnt = 0; s_last = 0ull; }
    __syncthreads();

    unsigned prefix = 0, pmask = 0;
    int need = 20;

    for (int pass = 0; pass < 3; pass++) {
        int shift = 24 - 8 * pass;
        hist[tid] = 0;
        __syncthreads();
        for (int j = tid; j < 4096; j += 256) {
            unsigned u = skey[j];
            if ((u & pmask) == prefix) atomicAdd(&hist[(u >> shift) & 255u], 1);
        }
        __syncthreads();
        int v = hist[tid];
#pragma unroll
        for (int off = 1; off < 256; off <<= 1) {
            int t = (tid >= off) ? hist[tid - off] : 0;
            __syncthreads();
            v += t; hist[tid] = v;
            __syncthreads();
        }
        int excl_self = tid ? hist[tid - 1] : 0;
        if (excl_self < need && hist[tid] >= need) sb = tid;
        __syncthreads();
        int b = sb;
        int excl = b ? hist[b - 1] : 0;
        for (int j = tid; j < 4096; j += 256) {
            unsigned u = skey[j];
            if ((u & pmask) == prefix && ((u >> shift) & 255u) < (unsigned)b) {
                int p = atomicAdd(&socnt, 1);
                orow[p] = j;
            }
        }
        prefix |= (unsigned)b << shift;
        pmask |= 0xFFu << shift;
        need -= excl;
        __syncthreads();
    }

    if (tid == 0) sccnt = 0;
    __syncthreads();
    for (int j = tid; j < 4096; j += 256) {
        if ((skey[j] & pmask) == prefix) {
            int p = atomicAdd(&sccnt, 1);
            if (p < 2048) cand[p] = j;
        }
    }
    __syncthreads();
    int m = sccnt;
    bool fits = (m <= 2048);
    int obase = socnt;

    for (int t = 0; t < need; t++) {
        unsigned long long last = s_last;
        unsigned long long best = ~0ull;
        if (fits) {
            for (int c = tid; c < m; c += 256) {
                int j = cand[c];
                unsigned long long key = ((unsigned long long)skey[j] << 32) | (unsigned)j;
                if (key > last && key < best) best = key;
            }
        } else {
            for (int j = tid; j < 4096; j += 256) {
                unsigned u = skey[j];
                if ((u & pmask) == prefix) {
                    unsigned long long key = ((unsigned long long)u << 32) | (unsigned)j;
                    if (key > last && key < best) best = key;
                }
            }
        }
#pragma unroll
        for (int off = 16; off; off >>= 1) {
            unsigned long long o = __shfl_down_sync(0xffffffffu, best, off);
            if (o < best) best = o;
        }
        if (lane == 0) wred[warp] = best;
        __syncthreads();
        if (tid == 0) {
            unsigned long long bb = wred[0];
#pragma unroll
            for (int w = 1; w < 8; w++) if (wred[w] < bb) bb = wred[w];
            orow[obase + t] = (int)(bb & 0xffffffffu);
            s_last = bb;
        }
        __syncthreads();
    }
}

// ---------------- weight pack: wp[0:O][c]=w[o][c], wp[O:2O][c]=w[o][C+c]-w[o][c] ------
__global__ void wpack_k(const float* __restrict__ w, int C, int O, float* __restrict__ wp)
{
    int i = blockIdx.x * blockDim.x + threadIdx.x;
    if (i >= O * C) return;
    int o = i / C, c = i - o * C;
    float wa = w[o * 2 * C + c];
    wp[o * C + c] = wa;
    wp[(O + o) * C + c] = w[o * 2 * C + C + c] - wa;
}

// ---------------- edge gather + max + BN + leaky ----------------
__global__ void combine_k(const float* __restrict__ qp, int O,
                          const int* __restrict__ idx,
                          const float* __restrict__ sv, const float* __restrict__ bv,
                          float* __restrict__ out, int ldo)
{
    __shared__ int nb[20];
    int r = blockIdx.x;
    int base = (r >> 12) << 12;
    int tid = threadIdx.x;
    int ldq = 2 * O;
    if (tid < 20) nb[tid] = idx[(long)r * 20 + tid];
    __syncthreads();
    for (int o = tid; o < O; o += blockDim.x) {
        float m = -FLT_MAX;
#pragma unroll
        for (int kk = 0; kk < 20; kk++)
            m = fmaxf(m, qp[(long)(base + nb[kk]) * ldq + o]);
        float v = sv[o] * (m + qp[(long)r * ldq + O + o]) + bv[o];
        out[(long)r * ldo + o] = lrelu(v);
    }
}

// ---------------- global max over N (two-pass) ----------------
__global__ void gmax1_k(const float* __restrict__ emb, float* __restrict__ part)
{
    int b = blockIdx.x >> 4, sp = blockIdx.x & 15;
    int o = blockIdx.y * 256 + threadIdx.x;
    const float* e = emb + ((long)b * 4096 + (long)sp * 256) * 1024 + o;
    float m = -FLT_MAX;
    for (int n = 0; n < 256; n++) m = fmaxf(m, e[(long)n * 1024]);
    part[(long)blockIdx.x * 1024 + o] = m;
}
__global__ void gmax2_k(const float* __restrict__ part, float* __restrict__ glob)
{
    int b = blockIdx.x; int o = blockIdx.y * 256 + threadIdx.x;
    float m = -FLT_MAX;
    for (int sp = 0; sp < 16; sp++) m = fmaxf(m, part[(long)(b * 16 + sp) * 1024 + o]);
    glob[(long)b * 1024 + o] = m;
}

// ---------------- host helper ----------------
static void gemm(int mode,
                 const float* X, int ldx, long xbs,
                 const float* W, int ldw, long wbs,
                 float* Y, int ldy, long ybs,
                 int M, int K, int NO, int Z,
                 const float* sv, const float* bv,
                 const float* aux, int auxS)
{
    dim3 grid((NO + 127) / 128, (M + 127) / 128, Z);
    switch (mode) {
    case 0: gemm_t<0><<<grid, 256>>>(X, ldx, xbs, W, ldw, wbs, Y, ldy, ybs, M, K, NO, sv, bv, aux, auxS); break;
    case 1: gemm_t<1><<<grid, 256>>>(X, ldx, xbs, W, ldw, wbs, Y, ldy, ybs, M, K, NO, sv, bv, aux, auxS); break;
    case 2: gemm_t<2><<<grid, 256>>>(X, ldx, xbs, W, ldw, wbs, Y, ldy, ybs, M, K, NO, sv, bv, aux, auxS); break;
    case 3: gemm_t<3><<<grid, 256>>>(X, ldx, xbs, W, ldw, wbs, Y, ldy, ybs, M, K, NO, sv, bv, aux, auxS); break;
    case 4: gemm_t<4><<<grid, 256>>>(X, ldx, xbs, W, ldw, wbs, Y, ldy, ybs, M, K, NO, sv, bv, aux, auxS); break;
    }
}

extern "C" void kernel_launch(void* const* d_in, const int* in_sizes, int n_in,
                              void* d_out, int out_size)
{
    (void)in_sizes; (void)n_in; (void)out_size;
    const float* xyz = (const float*)d_in[0];
    const float* w1 = (const float*)d_in[2];  const float* s1 = (const float*)d_in[3];  const float* b1 = (const float*)d_in[4];
    const float* w2 = (const float*)d_in[5];  const float* s2 = (const float*)d_in[6];  const float* b2 = (const float*)d_in[7];
    const float* w3 = (const float*)d_in[8];  const float* s3 = (const float*)d_in[9];  const float* b3 = (const float*)d_in[10];
    const float* w4 = (const float*)d_in[11]; const float* s4 = (const float*)d_in[12]; const float* b4 = (const float*)d_in[13];
    const float* wf = (const float*)d_in[14]; const float* sf = (const float*)d_in[15]; const float* bf = (const float*)d_in[16];
    const float* we = (const float*)d_in[17]; const float* se = (const float*)d_in[18]; const float* be = (const float*)d_in[19];
    const float* wh1 = (const float*)d_in[20]; const float* sh1 = (const float*)d_in[21]; const float* bh1 = (const float*)d_in[22];
    const float* wh2 = (const float*)d_in[23]; const float* sh2 = (const float*)d_in[24]; const float* bh2 = (const float*)d_in[25];
    const float* wh3 = (const float*)d_in[26]; const float* bh3 = (const float*)d_in[27];
    float* out = (float*)d_out;

    float *gd, *gcat, *gqp, *gx2, *glocal, *gemb, *gpart, *gglob, *ggh, *gh1, *gh2, *gwp;
    int *gidx;
    cudaGetSymbolAddress((void**)&gd, g_d);
    cudaGetSymbolAddress((void**)&gcat, g_cat);
    cudaGetSymbolAddress((void**)&gqp, g_qp);
    cudaGetSymbolAddress((void**)&gx2, g_x2);
    cudaGetSymbolAddress((void**)&gidx, g_idx);
    cudaGetSymbolAddress((void**)&glocal, g_local);
    cudaGetSymbolAddress((void**)&gemb, g_emb);
    cudaGetSymbolAddress((void**)&gpart, g_part);
    cudaGetSymbolAddress((void**)&gglob, g_glob);
    cudaGetSymbolAddress((void**)&ggh, g_gh);
    cudaGetSymbolAddress((void**)&gh1, g_h1);
    cudaGetSymbolAddress((void**)&gh2, g_h2);
    cudaGetSymbolAddress((void**)&gwp, g_wp);

    const int B = 4, N = 4096, M = B * N;

    auto edge_layer = [&](const float* X, int ldx, int C,
                          const float* w, const float* sv, const float* bv,
                          int O, float* outCol) {
        wpack_k<<<(O * C + 255) / 256, 256>>>(w, C, O, gwp);
        sqnorm_k<<<M / 8, 256>>>(X, ldx, C, gx2);
        gemm(2, X, ldx, (long)N * ldx, X, ldx, (long)N * ldx,
             gd, N, (long)N * N, N, C, N, B, nullptr, nullptr, gx2, N);
        topk_k<<<M, 256>>>(gd, gidx);
        // [q|p] = X * [w1 ; (w2-w1)]^T  -> [M, 2O]
        gemm(0, X, ldx, 0, gwp, C, 0, gqp, 2 * O, 0, M, C, 2 * O, 1, nullptr, nullptr, nullptr, 0);
        combine_k<<<M, 128>>>(gqp, O, gidx, sv, bv, outCol, 512);
    };

    edge_layer(xyz,        3,   3,   w1, s1, b1, 64,  gcat + 0);
    edge_layer(gcat + 0,   512, 64,  w2, s2, b2, 64,  gcat + 64);
    edge_layer(gcat + 64,  512, 64,  w3, s3, b3, 128, gcat + 128);
    edge_layer(gcat + 128, 512, 128, w4, s4, b4, 256, gcat + 256);

    gemm(1, gcat, 512, 0, wf, 512, 0, glocal, 512, 0, M, 512, 512, 1, sf, bf, nullptr, 0);
    gemm(1, glocal, 512, 0, we, 512, 0, gemb, 1024, 0, M, 512, 1024, 1, se, be, nullptr, 0);
    { dim3 g1(64, 4); gmax1_k<<<g1, 256>>>(gemb, gpart); }
    { dim3 g2(4, 4);  gmax2_k<<<g2, 256>>>(gpart, gglob); }
    gemm(0, gglob, 1024, 0, wh1 + 512, 1536, 0, ggh, 256, 0, B, 1024, 256, 1, nullptr, nullptr, nullptr, 0);
    gemm(3, glocal, 512, 0, wh1, 1536, 0, gh1, 256, 0, M, 512, 256, 1, sh1, bh1, ggh, 256);
    gemm(1, gh1, 256, 0, wh2, 256, 0, gh2, 256, 0, M, 256, 256, 1, sh2, bh2, nullptr, 0);
    gemm(4, gh2, 256, 0, wh3, 256, 0, out, 50, 0, M, 256, 50, 1, nullptr, bh3, nullptr, 0);
}

// round 7
// speedup vs baseline: 1.7433x; 1.1735x over previous
#include <cuda_runtime.h>
#include <cuda_bf16.h>
#include <cfloat>

#define LEAKF 0.2f

// ---------------- device scratch (no allocation allowed) ----------------
__device__ float g_d[4L * 4096 * 4096];   // 256 MB distance matrices
__device__ float g_cat[16384L * 512];     // x1|x2|x3|x4 concat, ld=512
__device__ float g_qp[16384L * 512];      // [q|p] packed, ld = 2*O
__device__ float g_x2[16384];
__device__ int   g_idx[16384L * 20];
__device__ float g_local[16384L * 512];
__device__ float g_emb[16384L * 1024];
__device__ float g_part[64L * 1024];
__device__ float g_glob[4L * 1024];
__device__ float g_gh[4L * 256];
__device__ float g_h1[16384L * 256];
__device__ float g_h2[16384L * 256];
__device__ float g_wp[512 * 128];         // packed [w1; w2-w1], max 2*256 x 128

__device__ __forceinline__ float lrelu(float v) { return v > 0.f ? v : LEAKF * v; }

__device__ __forceinline__ unsigned f2tf32(float v) {
    unsigned r;
    asm("cvt.rna.tf32.f32 %0, %1;" : "=r"(r) : "f"(v));
    return r;
}

// ---------------- 128x128 3xTF32 tensor-core GEMM with fused epilogues -------------
// Y[m][n] = sum_k X[m][k] * W[n][k]   (both row-major, arbitrary ld, batched via z)
// 3xTF32: x = hi + lo (both tf32);  x*y ~= xh*yh + xh*yl + xl*yh  -> ~fp32 precision.
// MODE 0: Y = acc
// MODE 1: Y = leaky(acc*s[n] + b[n])
// MODE 2: Y = x2[m] + x2[n] - 2*acc          (pairwise sq. distance; aux=x2, per-z)
// MODE 3: Y = leaky(s[n]*(acc + aux[(m>>12)*auxS + n]) + b[n])
// MODE 4: Y = acc + b[n]
// SYM=1 (MODE 2 only): X==W symmetric output; grid.x enumerates upper-triangle
// 128x128 tile pairs; epilogue mirrors writes. MMA accumulation order identical
// for (m,n) and (n,m) -> bitwise-equal values, benign duplicate diagonal writes.
// 8 warps: warp tile 32(m) x 64(n); mma.m16n8k8.tf32, fp32 accumulate.
#define SPAD 20
template<int MODE, int SYM>
__global__ __launch_bounds__(256, 2)
void gemm_t(const float* __restrict__ X, int ldx, long xbs,
            const float* __restrict__ W, int ldw, long wbs,
            float* __restrict__ Y, int ldy, long ybs,
            int M, int K, int NO,
            const float* __restrict__ sv,
            const float* __restrict__ bv,
            const float* __restrict__ aux, int auxS)
{
    __shared__ unsigned Ah[128 * SPAD];
    __shared__ unsigned Bh[128 * SPAD];
    __shared__ unsigned Al[128 * SPAD];
    __shared__ unsigned Bl[128 * SPAD];

    int z = blockIdx.z;
    const float* Xb = X + (long)z * xbs;
    const float* Wb = W + (long)z * wbs;
    float* Yb = Y + (long)z * ybs;

    int row0, col0;
    if (SYM) {
        // map linear blockIdx.x -> upper-triangle tile (bi, bj), bi <= bj
        int T = (M + 127) >> 7;
        int t = blockIdx.x;
        float ff = (float)(2 * T + 1);
        int bi = (int)((ff - sqrtf(ff * ff - 8.f * (float)t)) * 0.5f);
        // fix-up against float error
        while ((bi + 1) * T - ((bi + 1) * bi) / 2 <= t) bi++;
        while (bi * T - (bi * (bi - 1)) / 2 > t) bi--;
        int bj = bi + (t - (bi * T - (bi * (bi - 1)) / 2));
        row0 = bi << 7;
        col0 = bj << 7;
    } else {
        row0 = blockIdx.y * 128;
        col0 = blockIdx.x * 128;
    }

    int tid = threadIdx.x;
    int lane = tid & 31, wid = tid >> 5;
    int wm = wid & 3;        // 4 m-tiles of 32
    int wn = wid >> 2;       // 2 n-tiles of 64
    int grp = lane >> 2, tig = lane & 3;

    float acc[2][8][4];
#pragma unroll
    for (int h = 0; h < 2; h++)
#pragma unroll
        for (int j = 0; j < 8; j++)
#pragma unroll
            for (int c = 0; c < 4; c++) acc[h][j][c] = 0.f;

    int nchunks = (K + 15) >> 4;
    for (int ch = 0; ch < nchunks; ch++) {
        int k0 = ch << 4;
#pragma unroll
        for (int i = 0; i < 8; i++) {
            int li = tid * 8 + i;          // 0..2047
            int rrow = li >> 4, rcol = li & 15;
            int gk = k0 + rcol;
            int gm = row0 + rrow;
            float va = (gm < M && gk < K) ? Xb[(long)gm * ldx + gk] : 0.f;
            unsigned vah = f2tf32(va);
            Ah[rrow * SPAD + rcol] = vah;
            Al[rrow * SPAD + rcol] = f2tf32(va - __uint_as_float(vah));
            int gn = col0 + rrow;
            float vb = (gn < NO && gk < K) ? Wb[(long)gn * ldw + gk] : 0.f;
            unsigned vbh = f2tf32(vb);
            Bh[rrow * SPAD + rcol] = vbh;
            Bl[rrow * SPAD + rcol] = f2tf32(vb - __uint_as_float(vbh));
        }
        __syncthreads();

#pragma unroll
        for (int ks = 0; ks < 16; ks += 8) {
            unsigned ah[2][4], al[2][4];
#pragma unroll
            for (int h = 0; h < 2; h++) {
                int mb = wm * 32 + h * 16;
                int i0 = (mb + grp) * SPAD + ks + tig;
                int i1 = (mb + grp + 8) * SPAD + ks + tig;
                ah[h][0] = Ah[i0]; ah[h][1] = Ah[i1];
                ah[h][2] = Ah[i0 + 4]; ah[h][3] = Ah[i1 + 4];
                al[h][0] = Al[i0]; al[h][1] = Al[i1];
                al[h][2] = Al[i0 + 4]; al[h][3] = Al[i1 + 4];
            }
#pragma unroll
            for (int j = 0; j < 8; j++) {
                int nb = wn * 64 + j * 8;
                int ib = (nb + grp) * SPAD + ks + tig;
                unsigned bh0 = Bh[ib], bh1 = Bh[ib + 4];
                unsigned bl0 = Bl[ib], bl1 = Bl[ib + 4];
#pragma unroll
                for (int h = 0; h < 2; h++) {
                    asm volatile(
                        "mma.sync.aligned.m16n8k8.row.col.f32.tf32.tf32.f32 "
                        "{%0,%1,%2,%3}, {%4,%5,%6,%7}, {%8,%9}, {%0,%1,%2,%3};"
                        : "+f"(acc[h][j][0]), "+f"(acc[h][j][1]),
                          "+f"(acc[h][j][2]), "+f"(acc[h][j][3])
                        : "r"(al[h][0]), "r"(al[h][1]), "r"(al[h][2]), "r"(al[h][3]),
                          "r"(bh0), "r"(bh1));
                    asm volatile(
                        "mma.sync.aligned.m16n8k8.row.col.f32.tf32.tf32.f32 "
                        "{%0,%1,%2,%3}, {%4,%5,%6,%7}, {%8,%9}, {%0,%1,%2,%3};"
                        : "+f"(acc[h][j][0]), "+f"(acc[h][j][1]),
                          "+f"(acc[h][j][2]), "+f"(acc[h][j][3])
                        : "r"(ah[h][0]), "r"(ah[h][1]), "r"(ah[h][2]), "r"(ah[h][3]),
                          "r"(bl0), "r"(bl1));
                    asm volatile(
                        "mma.sync.aligned.m16n8k8.row.col.f32.tf32.tf32.f32 "
                        "{%0,%1,%2,%3}, {%4,%5,%6,%7}, {%8,%9}, {%0,%1,%2,%3};"
                        : "+f"(acc[h][j][0]), "+f"(acc[h][j][1]),
                          "+f"(acc[h][j][2]), "+f"(acc[h][j][3])
                        : "r"(ah[h][0]), "r"(ah[h][1]), "r"(ah[h][2]), "r"(ah[h][3]),
                          "r"(bh0), "r"(bh1));
                }
            }
        }
        __syncthreads();
    }

    // epilogue
#pragma unroll
    for (int h = 0; h < 2; h++) {
        int r0 = row0 + wm * 32 + h * 16 + grp;
#pragma unroll
        for (int j = 0; j < 8; j++) {
            int cb = col0 + wn * 64 + j * 8 + 2 * tig;
#pragma unroll
            for (int half = 0; half < 2; half++) {
                int gm = r0 + half * 8;
                if (gm >= M) continue;
#pragma unroll
                for (int cc = 0; cc < 2; cc++) {
                    int gn = cb + cc;
                    if (gn >= NO) continue;
                    float v = acc[h][j][half * 2 + cc];
                    if (MODE == 1) v = lrelu(v * sv[gn] + bv[gn]);
                    else if (MODE == 2) {
                        const float* x2 = aux + (long)z * auxS;
                        v = x2[gm] + x2[gn] - 2.f * v;
                    } else if (MODE == 3) {
                        int bb = gm >> 12;
                        v = lrelu(sv[gn] * (v + aux[bb * auxS + gn]) + bv[gn]);
                    } else if (MODE == 4) v = v + bv[gn];
                    Yb[(long)gm * ldy + gn] = v;
                    if (SYM) Yb[(long)gn * ldy + gm] = v;
                }
            }
        }
    }
}

// ---------------- squared norms (warp per row) ----------------
__global__ void sqnorm_k(const float* __restrict__ X, int ldx, int C, float* __restrict__ x2)
{
    int warp = (blockIdx.x * blockDim.x + threadIdx.x) >> 5;
    int lane = threadIdx.x & 31;
    if (warp >= 16384) return;
    const float* xr = X + (long)warp * ldx;
    float s = 0.f;
    for (int c = lane; c < C; c += 32) { float v = xr[c]; s = fmaf(v, v, s); }
#pragma unroll
    for (int off = 16; off; off >>= 1) s += __shfl_down_sync(0xffffffffu, s, off);
    if (lane == 0) x2[warp] = s;
}

// ---------------- top-20 smallest via 3-level radix select ----------------
__global__ __launch_bounds__(256) void topk_k(const float* __restrict__ D, int* __restrict__ idx)
{
    __shared__ unsigned skey[4096];
    __shared__ int hist[256];
    __shared__ int cand[2048];
    __shared__ int sb, socnt, sccnt;
    __shared__ unsigned long long wred[8];
    __shared__ unsigned long long s_last;

    long r = blockIdx.x;
    const float* drow = D + r * 4096;
    int* orow = idx + r * 20;
    int tid = threadIdx.x;
    int lane = tid & 31, warp = tid >> 5;

    for (int j = tid; j < 4096; j += 256)
        skey[j] = __float_as_uint(fmaxf(drow[j], 0.f));
    if (tid == 0) { socnt = 0; s_last = 0ull; }
    __syncthreads();

    unsigned prefix = 0, pmask = 0;
    int need = 20;

    for (int pass = 0; pass < 3; pass++) {
        int shift = 24 - 8 * pass;
        hist[tid] = 0;
        __syncthreads();
        for (int j = tid; j < 4096; j += 256) {
            unsigned u = skey[j];
            if ((u & pmask) == prefix) atomicAdd(&hist[(u >> shift) & 255u], 1);
        }
        __syncthreads();
        int v = hist[tid];
#pragma unroll
        for (int off = 1; off < 256; off <<= 1) {
            int t = (tid >= off) ? hist[tid - off] : 0;
            __syncthreads();
            v += t; hist[tid] = v;
            __syncthreads();
        }
        int excl_self = tid ? hist[tid - 1] : 0;
        if (excl_self < need && hist[tid] >= need) sb = tid;
        __syncthreads();
        int b = sb;
        int excl = b ? hist[b - 1] : 0;
        for (int j = tid; j < 4096; j += 256) {
            unsigned u = skey[j];
            if ((u & pmask) == prefix && ((u >> shift) & 255u) < (unsigned)b) {
                int p = atomicAdd(&socnt, 1);
                orow[p] = j;
            }
        }
        prefix |= (unsigned)b << shift;
        pmask |= 0xFFu << shift;
        need -= excl;
        __syncthreads();
    }

    if (tid == 0) sccnt = 0;
    __syncthreads();
    for (int j = tid; j < 4096; j += 256) {
        if ((skey[j] & pmask) == prefix) {
            int p = atomicAdd(&sccnt, 1);
            if (p < 2048) cand[p] = j;
        }
    }
    __syncthreads();
    int m = sccnt;
    bool fits = (m <= 2048);
    int obase = socnt;

    for (int t = 0; t < need; t++) {
        unsigned long long last = s_last;
        unsigned long long best = ~0ull;
        if (fits) {
            for (int c = tid; c < m; c += 256) {
                int j = cand[c];
                unsigned long long key = ((unsigned long long)skey[j] << 32) | (unsigned)j;
                if (key > last && key < best) best = key;
            }
        } else {
            for (int j = tid; j < 4096; j += 256) {
                unsigned u = skey[j];
                if ((u & pmask) == prefix) {
                    unsigned long long key = ((unsigned long long)u << 32) | (unsigned)j;
                    if (key > last && key < best) best = key;
                }
            }
        }
#pragma unroll
        for (int off = 16; off; off >>= 1) {
            unsigned long long o = __shfl_down_sync(0xffffffffu, best, off);
            if (o < best) best = o;
        }
        if (lane == 0) wred[warp] = best;
        __syncthreads();
        if (tid == 0) {
            unsigned long long bb = wred[0];
#pragma unroll
            for (int w = 1; w < 8; w++) if (wred[w] < bb) bb = wred[w];
            orow[obase + t] = (int)(bb & 0xffffffffu);
            s_last = bb;
        }
        __syncthreads();
    }
}

// ---------------- weight pack: wp[0:O][c]=w[o][c], wp[O:2O][c]=w[o][C+c]-w[o][c] ------
__global__ void wpack_k(const float* __restrict__ w, int C, int O, float* __restrict__ wp)
{
    int i = blockIdx.x * blockDim.x + threadIdx.x;
    if (i >= O * C) return;
    int o = i / C, c = i - o * C;
    float wa = w[o * 2 * C + c];
    wp[o * C + c] = wa;
    wp[(O + o) * C + c] = w[o * 2 * C + C + c] - wa;
}

// ---------------- edge gather + max + BN + leaky ----------------
__global__ void combine_k(const float* __restrict__ qp, int O,
                          const int* __restrict__ idx,
                          const float* __restrict__ sv, const float* __restrict__ bv,
                          float* __restrict__ out, int ldo)
{
    __shared__ int nb[20];
    int r = blockIdx.x;
    int base = (r >> 12) << 12;
    int tid = threadIdx.x;
    int ldq = 2 * O;
    if (tid < 20) nb[tid] = idx[(long)r * 20 + tid];
    __syncthreads();
    for (int o = tid; o < O; o += blockDim.x) {
        float m = -FLT_MAX;
#pragma unroll
        for (int kk = 0; kk < 20; kk++)
            m = fmaxf(m, qp[(long)(base + nb[kk]) * ldq + o]);
        float v = sv[o] * (m + qp[(long)r * ldq + O + o]) + bv[o];
        out[(long)r * ldo + o] = lrelu(v);
    }
}

// ---------------- global max over N (two-pass) ----------------
__global__ void gmax1_k(const float* __restrict__ emb, float* __restrict__ part)
{
    int b = blockIdx.x >> 4, sp = blockIdx.x & 15;
    int o = blockIdx.y * 256 + threadIdx.x;
    const float* e = emb + ((long)b * 4096 + (long)sp * 256) * 1024 + o;
    float m = -FLT_MAX;
    for (int n = 0; n < 256; n++) m = fmaxf(m, e[(long)n * 1024]);
    part[(long)blockIdx.x * 1024 + o] = m;
}
__global__ void gmax2_k(const float* __restrict__ part, float* __restrict__ glob)
{
    int b = blockIdx.x; int o = blockIdx.y * 256 + threadIdx.x;
    float m = -FLT_MAX;
    for (int sp = 0; sp < 16; sp++) m = fmaxf(m, part[(long)(b * 16 + sp) * 1024 + o]);
    glob[(long)b * 1024 + o] = m;
}

// ---------------- host helpers ----------------
static void gemm(int mode,
                 const float* X, int ldx, long xbs,
                 const float* W, int ldw, long wbs,
                 float* Y, int ldy, long ybs,
                 int M, int K, int NO, int Z,
                 const float* sv, const float* bv,
                 const float* aux, int auxS)
{
    dim3 grid((NO + 127) / 128, (M + 127) / 128, Z);
    switch (mode) {
    case 0: gemm_t<0,0><<<grid, 256>>>(X, ldx, xbs, W, ldw, wbs, Y, ldy, ybs, M, K, NO, sv, bv, aux, auxS); break;
    case 1: gemm_t<1,0><<<grid, 256>>>(X, ldx, xbs, W, ldw, wbs, Y, ldy, ybs, M, K, NO, sv, bv, aux, auxS); break;
    case 3: gemm_t<3,0><<<grid, 256>>>(X, ldx, xbs, W, ldw, wbs, Y, ldy, ybs, M, K, NO, sv, bv, aux, auxS); break;
    case 4: gemm_t<4,0><<<grid, 256>>>(X, ldx, xbs, W, ldw, wbs, Y, ldy, ybs, M, K, NO, sv, bv, aux, auxS); break;
    }
}

static void gemm_dist_sym(const float* X, int ldx, long xbs,
                          float* Y, int ldy, long ybs,
                          int N, int K, int Z, const float* x2, int auxS)
{
    int T = (N + 127) / 128;
    dim3 grid(T * (T + 1) / 2, 1, Z);
    gemm_t<2,1><<<grid, 256>>>(X, ldx, xbs, X, ldx, xbs, Y, ldy, ybs, N, K, N,
                               nullptr, nullptr, x2, auxS);
}

extern "C" void kernel_launch(void* const* d_in, const int* in_sizes, int n_in,
                              void* d_out, int out_size)
{
    (void)in_sizes; (void)n_in; (void)out_size;
    const float* xyz = (const float*)d_in[0];
    const float* w1 = (const float*)d_in[2];  const float* s1 = (const float*)d_in[3];  const float* b1 = (const float*)d_in[4];
    const float* w2 = (const float*)d_in[5];  const float* s2 = (const float*)d_in[6];  const float* b2 = (const float*)d_in[7];
    const float* w3 = (const float*)d_in[8];  const float* s3 = (const float*)d_in[9];  const float* b3 = (const float*)d_in[10];
    const float* w4 = (const float*)d_in[11]; const float* s4 = (const float*)d_in[12]; const float* b4 = (const float*)d_in[13];
    const float* wf = (const float*)d_in[14]; const float* sf = (const float*)d_in[15]; const float* bf = (const float*)d_in[16];
    const float* we = (const float*)d_in[17]; const float* se = (const float*)d_in[18]; const float* be = (const float*)d_in[19];
    const float* wh1 = (const float*)d_in[20]; const float* sh1 = (const float*)d_in[21]; const float* bh1 = (const float*)d_in[22];
    const float* wh2 = (const float*)d_in[23]; const float* sh2 = (const float*)d_in[24]; const float* bh2 = (const float*)d_in[25];
    const float* wh3 = (const float*)d_in[26]; const float* bh3 = (const float*)d_in[27];
    float* out = (float*)d_out;

    float *gd, *gcat, *gqp, *gx2, *glocal, *gemb, *gpart, *gglob, *ggh, *gh1, *gh2, *gwp;
    int *gidx;
    cudaGetSymbolAddress((void**)&gd, g_d);
    cudaGetSymbolAddress((void**)&gcat, g_cat);
    cudaGetSymbolAddress((void**)&gqp, g_qp);
    cudaGetSymbolAddress((void**)&gx2, g_x2);
    cudaGetSymbolAddress((void**)&gidx, g_idx);
    cudaGetSymbolAddress((void**)&glocal, g_local);
    cudaGetSymbolAddress((void**)&gemb, g_emb);
    cudaGetSymbolAddress((void**)&gpart, g_part);
    cudaGetSymbolAddress((void**)&gglob, g_glob);
    cudaGetSymbolAddress((void**)&ggh, g_gh);
    cudaGetSymbolAddress((void**)&gh1, g_h1);
    cudaGetSymbolAddress((void**)&gh2, g_h2);
    cudaGetSymbolAddress((void**)&gwp, g_wp);

    const int B = 4, N = 4096, M = B * N;

    auto edge_layer = [&](const float* X, int ldx, int C,
                          const float* w, const float* sv, const float* bv,
                          int O, float* outCol) {
        wpack_k<<<(O * C + 255) / 256, 256>>>(w, C, O, gwp);
        sqnorm_k<<<M / 8, 256>>>(X, ldx, C, gx2);
        gemm_dist_sym(X, ldx, (long)N * ldx, gd, N, (long)N * N, N, C, B, gx2, N);
        topk_k<<<M, 256>>>(gd, gidx);
        // [q|p] = X * [w1 ; (w2-w1)]^T  -> [M, 2O]
        gemm(0, X, ldx, 0, gwp, C, 0, gqp, 2 * O, 0, M, C, 2 * O, 1, nullptr, nullptr, nullptr, 0);
        combine_k<<<M, 128>>>(gqp, O, gidx, sv, bv, outCol, 512);
    };

    edge_layer(xyz,        3,   3,   w1, s1, b1, 64,  gcat + 0);
    edge_layer(gcat + 0,   512, 64,  w2, s2, b2, 64,  gcat + 64);
    edge_layer(gcat + 64,  512, 64,  w3, s3, b3, 128, gcat + 128);
    edge_layer(gcat + 128, 512, 128, w4, s4, b4, 256, gcat + 256);

    gemm(1, gcat, 512, 0, wf, 512, 0, glocal, 512, 0, M, 512, 512, 1, sf, bf, nullptr, 0);
    gemm(1, glocal, 512, 0, we, 512, 0, gemb, 1024, 0, M, 512, 1024, 1, se, be, nullptr, 0);
    { dim3 g1(64, 4); gmax1_k<<<g1, 256>>>(gemb, gpart); }
    { dim3 g2(4, 4);  gmax2_k<<<g2, 256>>>(gpart, gglob); }
    gemm(0, gglob, 1024, 0, wh1 + 512, 1536, 0, ggh, 256, 0, B, 1024, 256, 1, nullptr, nullptr, nullptr, 0);
    gemm(3, glocal, 512, 0, wh1, 1536, 0, gh1, 256, 0, M, 512, 256, 1, sh1, bh1, ggh, 256);
    gemm(1, gh1, 256, 0, wh2, 256, 0, gh2, 256, 0, M, 256, 256, 1, sh2, bh2, nullptr, 0);
    gemm(4, gh2, 256, 0, wh3, 256, 0, out, 50, 0, M, 256, 50, 1, nullptr, bh3, nullptr, 0);
}

// round 8
// speedup vs baseline: 2.2747x; 1.3049x over previous
#include <cuda_runtime.h>
#include <cuda_bf16.h>
#include <cfloat>

#define LEAKF 0.2f
#define SPAD 20
#define PLANE (128 * SPAD)          // unsigned elems per smem plane
#define PLANEB (PLANE * 4)          // bytes
#define STAGEB (4 * PLANEB)         // bytes per stage (Ah,Al,Bh,Bl)
#define SMEM_DYN (2 * STAGEB)       // 81920 bytes

// ---------------- device scratch (no allocation allowed) ----------------
__device__ float g_d[4L * 4096 * 4096];   // 256 MB distance matrices
__device__ float g_cat[16384L * 512];
__device__ float g_qp[16384L * 512];
__device__ float g_x2[16384];
__device__ int   g_idx[16384L * 20];
__device__ float g_local[16384L * 512];
__device__ float g_emb[16384L * 1024];
__device__ float g_part[64L * 1024];
__device__ float g_glob[4L * 1024];
__device__ float g_gh[4L * 256];
__device__ float g_h1[16384L * 256];
__device__ float g_h2[16384L * 256];
__device__ float g_wp[512 * 128];
__device__ unsigned g_ah[16384L * 512];   // activation hi (tf32 bits), dense ld=K16
__device__ unsigned g_al[16384L * 512];   // activation lo
__device__ unsigned g_bh[1024L * 1536];   // weight hi
__device__ unsigned g_bl[1024L * 1536];   // weight lo

__device__ __forceinline__ float lrelu(float v) { return v > 0.f ? v : LEAKF * v; }

__device__ __forceinline__ unsigned f2tf32(float v) {
    unsigned r;
    asm("cvt.rna.tf32.f32 %0, %1;" : "=r"(r) : "f"(v));
    return r;
}

__device__ __forceinline__ void cpasync16(unsigned saddr, const void* g) {
    asm volatile("cp.async.ca.shared.global [%0], [%1], 16;" :: "r"(saddr), "l"(g));
}
__device__ __forceinline__ void cpcommit() { asm volatile("cp.async.commit_group;"); }
template<int N>
__device__ __forceinline__ void cpwait() { asm volatile("cp.async.wait_group %0;" :: "n"(N)); }

// ---------------- tf32 hi/lo pre-decomposition ----------------
// src [rows x ld] (use C cols) -> oh/ol [rowspad x K16], zero-padded.
__global__ void conv_k(const float* __restrict__ src, int ld, int rows, int C,
                       int K16, unsigned* __restrict__ oh, unsigned* __restrict__ ol)
{
    int r = blockIdx.x;
    for (int c = threadIdx.x; c < K16; c += blockDim.x) {
        float v = (r < rows && c < C) ? src[(long)r * ld + c] : 0.f;
        unsigned h = f2tf32(v);
        long i = (long)r * K16 + c;
        oh[i] = h;
        ol[i] = f2tf32(v - __uint_as_float(h));
    }
}

// ---------------- 128x128 3xTF32 MMA GEMM, cp.async double-buffered --------------
// Inputs pre-decomposed (hi/lo tf32 bits), dense, zero-padded: rows mult-128
// coverage guaranteed by conversion buffers, K16 mult-16.
// MODE 0: Y = acc
// MODE 1: Y = leaky(acc*s[n] + b[n])
// MODE 2: Y = x2[m] + x2[n] - 2*acc  (SYM=1: upper-tri tiles, mirrored writes)
// MODE 3: Y = leaky(s[n]*(acc + aux[(m>>12)*auxS + n]) + b[n])
// MODE 4: Y = acc + b[n]
template<int MODE, int SYM>
__global__ __launch_bounds__(256, 2)
void gemm_cp(const unsigned* __restrict__ Agh, const unsigned* __restrict__ Agl,
             int lda, long abs_,
             const unsigned* __restrict__ Bgh, const unsigned* __restrict__ Bgl,
             int ldb, long bbs,
             float* __restrict__ Y, int ldy, long ybs,
             int M, int K16, int NO,
             const float* __restrict__ sv, const float* __restrict__ bv,
             const float* __restrict__ aux, int auxS)
{
    extern __shared__ unsigned smd[];
    unsigned sb32 = (unsigned)__cvta_generic_to_shared(smd);

    int z = blockIdx.z;
    const unsigned* Ah_g = Agh + (long)z * abs_;
    const unsigned* Al_g = Agl + (long)z * abs_;
    const unsigned* Bh_g = Bgh + (long)z * bbs;
    const unsigned* Bl_g = Bgl + (long)z * bbs;
    float* Yb = Y + (long)z * ybs;

    int row0, col0;
    if (SYM) {
        int T = (M + 127) >> 7;
        int t = blockIdx.x;
        float ff = (float)(2 * T + 1);
        int bi = (int)((ff - sqrtf(ff * ff - 8.f * (float)t)) * 0.5f);
        while ((bi + 1) * T - ((bi + 1) * bi) / 2 <= t) bi++;
        while (bi * T - (bi * (bi - 1)) / 2 > t) bi--;
        int bj = bi + (t - (bi * T - (bi * (bi - 1)) / 2));
        row0 = bi << 7;
        col0 = bj << 7;
    } else {
        row0 = blockIdx.y * 128;
        col0 = blockIdx.x * 128;
    }

    int tid = threadIdx.x;
    int lane = tid & 31, wid = tid >> 5;
    int wm = wid & 3, wn = wid >> 2;
    int grp = lane >> 2, tig = lane & 3;

    float acc[2][8][4];
#pragma unroll
    for (int h = 0; h < 2; h++)
#pragma unroll
        for (int j = 0; j < 8; j++)
#pragma unroll
            for (int c = 0; c < 4; c++) acc[h][j][c] = 0.f;

    int nch = K16 >> 4;

    // stage loader: 8 x 16B cp.async per thread
    auto load_stage = [&](int stage, int k0) {
        unsigned base = sb32 + stage * STAGEB;
#pragma unroll
        for (int v = 0; v < 2; v++) {
            int vec = tid + v * 256;            // 0..511
            int row = vec >> 2, seg = (vec & 3) * 4;
            unsigned soff = (unsigned)(row * SPAD + seg) * 4u;
            long goa = (long)(row0 + row) * lda + k0 + seg;
            long gob = (long)(col0 + row) * ldb + k0 + seg;
            cpasync16(base + soff,              Ah_g + goa);
            cpasync16(base + PLANEB + soff,     Al_g + goa);
            cpasync16(base + 2 * PLANEB + soff, Bh_g + gob);
            cpasync16(base + 3 * PLANEB + soff, Bl_g + gob);
        }
        cpcommit();
    };

    load_stage(0, 0);

    for (int ch = 0; ch < nch; ch++) {
        int cur = ch & 1;
        if (ch + 1 < nch) load_stage(cur ^ 1, (ch + 1) << 4);
        if (ch + 1 < nch) cpwait<1>(); else cpwait<0>();
        __syncthreads();

        const unsigned* Ah = smd + cur * 4 * PLANE;
        const unsigned* Al = Ah + PLANE;
        const unsigned* Bh = Al + PLANE;
        const unsigned* Bl = Bh + PLANE;

#pragma unroll
        for (int ks = 0; ks < 16; ks += 8) {
            unsigned ah[2][4], al[2][4];
#pragma unroll
            for (int h = 0; h < 2; h++) {
                int mb = wm * 32 + h * 16;
                int i0 = (mb + grp) * SPAD + ks + tig;
                int i1 = (mb + grp + 8) * SPAD + ks + tig;
                ah[h][0] = Ah[i0]; ah[h][1] = Ah[i1];
                ah[h][2] = Ah[i0 + 4]; ah[h][3] = Ah[i1 + 4];
                al[h][0] = Al[i0]; al[h][1] = Al[i1];
                al[h][2] = Al[i0 + 4]; al[h][3] = Al[i1 + 4];
            }
#pragma unroll
            for (int j = 0; j < 8; j++) {
                int nb = wn * 64 + j * 8;
                int ib = (nb + grp) * SPAD + ks + tig;
                unsigned bh0 = Bh[ib], bh1 = Bh[ib + 4];
                unsigned bl0 = Bl[ib], bl1 = Bl[ib + 4];
#pragma unroll
                for (int h = 0; h < 2; h++) {
                    asm volatile(
                        "mma.sync.aligned.m16n8k8.row.col.f32.tf32.tf32.f32 "
                        "{%0,%1,%2,%3}, {%4,%5,%6,%7}, {%8,%9}, {%0,%1,%2,%3};"
                        : "+f"(acc[h][j][0]), "+f"(acc[h][j][1]),
                          "+f"(acc[h][j][2]), "+f"(acc[h][j][3])
                        : "r"(al[h][0]), "r"(al[h][1]), "r"(al[h][2]), "r"(al[h][3]),
                          "r"(bh0), "r"(bh1));
                    asm volatile(
                        "mma.sync.aligned.m16n8k8.row.col.f32.tf32.tf32.f32 "
                        "{%0,%1,%2,%3}, {%4,%5,%6,%7}, {%8,%9}, {%0,%1,%2,%3};"
                        : "+f"(acc[h][j][0]), "+f"(acc[h][j][1]),
                          "+f"(acc[h][j][2]), "+f"(acc[h][j][3])
                        : "r"(ah[h][0]), "r"(ah[h][1]), "r"(ah[h][2]), "r"(ah[h][3]),
                          "r"(bl0), "r"(bl1));
                    asm volatile(
                        "mma.sync.aligned.m16n8k8.row.col.f32.tf32.tf32.f32 "
                        "{%0,%1,%2,%3}, {%4,%5,%6,%7}, {%8,%9}, {%0,%1,%2,%3};"
                        : "+f"(acc[h][j][0]), "+f"(acc[h][j][1]),
                          "+f"(acc[h][j][2]), "+f"(acc[h][j][3])
                        : "r"(ah[h][0]), "r"(ah[h][1]), "r"(ah[h][2]), "r"(ah[h][3]),
                          "r"(bh0), "r"(bh1));
                }
            }
        }
        __syncthreads();
    }

    // epilogue
#pragma unroll
    for (int h = 0; h < 2; h++) {
        int r0 = row0 + wm * 32 + h * 16 + grp;
#pragma unroll
        for (int j = 0; j < 8; j++) {
            int cb = col0 + wn * 64 + j * 8 + 2 * tig;
#pragma unroll
            for (int half = 0; half < 2; half++) {
                int gm = r0 + half * 8;
                if (gm >= M) continue;
#pragma unroll
                for (int cc = 0; cc < 2; cc++) {
                    int gn = cb + cc;
                    if (gn >= NO) continue;
                    float v = acc[h][j][half * 2 + cc];
                    if (MODE == 1) v = lrelu(v * sv[gn] + bv[gn]);
                    else if (MODE == 2) {
                        const float* x2 = aux + (long)z * auxS;
                        v = x2[gm] + x2[gn] - 2.f * v;
                    } else if (MODE == 3) {
                        int bb = gm >> 12;
                        v = lrelu(sv[gn] * (v + aux[bb * auxS + gn]) + bv[gn]);
                    } else if (MODE == 4) v = v + bv[gn];
                    Yb[(long)gm * ldy + gn] = v;
                    if (SYM) Yb[(long)gn * ldy + gm] = v;
                }
            }
        }
    }
}

// ---------------- old scalar-load 3xTF32 GEMM (kept for the tiny 4x256 GEMM) ------
template<int MODE>
__global__ __launch_bounds__(256, 2)
void gemm_t(const float* __restrict__ X, int ldx,
            const float* __restrict__ W, int ldw,
            float* __restrict__ Y, int ldy,
            int M, int K, int NO)
{
    __shared__ unsigned Ah[128 * SPAD];
    __shared__ unsigned Bh[128 * SPAD];
    __shared__ unsigned Al[128 * SPAD];
    __shared__ unsigned Bl[128 * SPAD];

    int row0 = blockIdx.y * 128;
    int col0 = blockIdx.x * 128;
    int tid = threadIdx.x;
    int lane = tid & 31, wid = tid >> 5;
    int wm = wid & 3, wn = wid >> 2;
    int grp = lane >> 2, tig = lane & 3;

    float acc[2][8][4];
#pragma unroll
    for (int h = 0; h < 2; h++)
#pragma unroll
        for (int j = 0; j < 8; j++)
#pragma unroll
            for (int c = 0; c < 4; c++) acc[h][j][c] = 0.f;

    int nchunks = (K + 15) >> 4;
    for (int ch = 0; ch < nchunks; ch++) {
        int k0 = ch << 4;
#pragma unroll
        for (int i = 0; i < 8; i++) {
            int li = tid * 8 + i;
            int rrow = li >> 4, rcol = li & 15;
            int gk = k0 + rcol;
            int gm = row0 + rrow;
            float va = (gm < M && gk < K) ? X[(long)gm * ldx + gk] : 0.f;
            unsigned vah = f2tf32(va);
            Ah[rrow * SPAD + rcol] = vah;
            Al[rrow * SPAD + rcol] = f2tf32(va - __uint_as_float(vah));
            int gn = col0 + rrow;
            float vb = (gn < NO && gk < K) ? W[(long)gn * ldw + gk] : 0.f;
            unsigned vbh = f2tf32(vb);
            Bh[rrow * SPAD + rcol] = vbh;
            Bl[rrow * SPAD + rcol] = f2tf32(vb - __uint_as_float(vbh));
        }
        __syncthreads();
#pragma unroll
        for (int ks = 0; ks < 16; ks += 8) {
            unsigned ah[2][4], al[2][4];
#pragma unroll
            for (int h = 0; h < 2; h++) {
                int mb = wm * 32 + h * 16;
                int i0 = (mb + grp) * SPAD + ks + tig;
                int i1 = (mb + grp + 8) * SPAD + ks + tig;
                ah[h][0] = Ah[i0]; ah[h][1] = Ah[i1];
                ah[h][2] = Ah[i0 + 4]; ah[h][3] = Ah[i1 + 4];
                al[h][0] = Al[i0]; al[h][1] = Al[i1];
                al[h][2] = Al[i0 + 4]; al[h][3] = Al[i1 + 4];
            }
#pragma unroll
            for (int j = 0; j < 8; j++) {
                int nb = wn * 64 + j * 8;
                int ib = (nb + grp) * SPAD + ks + tig;
                unsigned bh0 = Bh[ib], bh1 = Bh[ib + 4];
                unsigned bl0 = Bl[ib], bl1 = Bl[ib + 4];
#pragma unroll
                for (int h = 0; h < 2; h++) {
                    asm volatile(
                        "mma.sync.aligned.m16n8k8.row.col.f32.tf32.tf32.f32 "
                        "{%0,%1,%2,%3}, {%4,%5,%6,%7}, {%8,%9}, {%0,%1,%2,%3};"
                        : "+f"(acc[h][j][0]), "+f"(acc[h][j][1]),
                          "+f"(acc[h][j][2]), "+f"(acc[h][j][3])
                        : "r"(al[h][0]), "r"(al[h][1]), "r"(al[h][2]), "r"(al[h][3]),
                          "r"(bh0), "r"(bh1));
                    asm volatile(
                        "mma.sync.aligned.m16n8k8.row.col.f32.tf32.tf32.f32 "
                        "{%0,%1,%2,%3}, {%4,%5,%6,%7}, {%8,%9}, {%0,%1,%2,%3};"
                        : "+f"(acc[h][j][0]), "+f"(acc[h][j][1]),
                          "+f"(acc[h][j][2]), "+f"(acc[h][j][3])
                        : "r"(ah[h][0]), "r"(ah[h][1]), "r"(ah[h][2]), "r"(ah[h][3]),
                          "r"(bl0), "r"(bl1));
                    asm volatile(
                        "mma.sync.aligned.m16n8k8.row.col.f32.tf32.tf32.f32 "
                        "{%0,%1,%2,%3}, {%4,%5,%6,%7}, {%8,%9}, {%0,%1,%2,%3};"
                        : "+f"(acc[h][j][0]), "+f"(acc[h][j][1]),
                          "+f"(acc[h][j][2]), "+f"(acc[h][j][3])
                        : "r"(ah[h][0]), "r"(ah[h][1]), "r"(ah[h][2]), "r"(ah[h][3]),
                          "r"(bh0), "r"(bh1));
                }
            }
        }
        __syncthreads();
    }
#pragma unroll
    for (int h = 0; h < 2; h++) {
        int r0 = row0 + wm * 32 + h * 16 + grp;
#pragma unroll
        for (int j = 0; j < 8; j++) {
            int cb = col0 + wn * 64 + j * 8 + 2 * tig;
#pragma unroll
            for (int half = 0; half < 2; half++) {
                int gm = r0 + half * 8;
                if (gm >= M) continue;
#pragma unroll
                for (int cc = 0; cc < 2; cc++) {
                    int gn = cb + cc;
                    if (gn >= NO) continue;
                    Y[(long)gm * ldy + gn] = acc[h][j][half * 2 + cc];
                }
            }
        }
    }
}

// ---------------- squared norms (warp per row) ----------------
__global__ void sqnorm_k(const float* __restrict__ X, int ldx, int C, float* __restrict__ x2)
{
    int warp = (blockIdx.x * blockDim.x + threadIdx.x) >> 5;
    int lane = threadIdx.x & 31;
    if (warp >= 16384) return;
    const float* xr = X + (long)warp * ldx;
    float s = 0.f;
    for (int c = lane; c < C; c += 32) { float v = xr[c]; s = fmaf(v, v, s); }
#pragma unroll
    for (int off = 16; off; off >>= 1) s += __shfl_down_sync(0xffffffffu, s, off);
    if (lane == 0) x2[warp] = s;
}

// ---------------- top-20 smallest via 3-level radix select ----------------
__global__ __launch_bounds__(256) void topk_k(const float* __restrict__ D, int* __restrict__ idx)
{
    __shared__ unsigned skey[4096];
    __shared__ int hist[256];
    __shared__ int cand[2048];
    __shared__ int sb, socnt, sccnt;
    __shared__ unsigned long long wred[8];
    __shared__ unsigned long long s_last;

    long r = blockIdx.x;
    const float* drow = D + r * 4096;
    int* orow = idx + r * 20;
    int tid = threadIdx.x;
    int lane = tid & 31, warp = tid >> 5;

    for (int j = tid; j < 4096; j += 256)
        skey[j] = __float_as_uint(fmaxf(drow[j], 0.f));
    if (tid == 0) { socnt = 0; s_last = 0ull; }
    __syncthreads();

    unsigned prefix = 0, pmask = 0;
    int need = 20;

    for (int pass = 0; pass < 3; pass++) {
        int shift = 24 - 8 * pass;
        hist[tid] = 0;
        __syncthreads();
        for (int j = tid; j < 4096; j += 256) {
            unsigned u = skey[j];
            if ((u & pmask) == prefix) atomicAdd(&hist[(u >> shift) & 255u], 1);
        }
        __syncthreads();
        int v = hist[tid];
#pragma unroll
        for (int off = 1; off < 256; off <<= 1) {
            int t = (tid >= off) ? hist[tid - off] : 0;
            __syncthreads();
            v += t; hist[tid] = v;
            __syncthreads();
        }
        int excl_self = tid ? hist[tid - 1] : 0;
        if (excl_self < need && hist[tid] >= need) sb = tid;
        __syncthreads();
        int b = sb;
        int excl = b ? hist[b - 1] : 0;
        for (int j = tid; j < 4096; j += 256) {
            unsigned u = skey[j];
            if ((u & pmask) == prefix && ((u >> shift) & 255u) < (unsigned)b) {
                int p = atomicAdd(&socnt, 1);
                orow[p] = j;
            }
        }
        prefix |= (unsigned)b << shift;
        pmask |= 0xFFu << shift;
        need -= excl;
        __syncthreads();
    }

    if (tid == 0) sccnt = 0;
    __syncthreads();
    for (int j = tid; j < 4096; j += 256) {
        if ((skey[j] & pmask) == prefix) {
            int p = atomicAdd(&sccnt, 1);
            if (p < 2048) cand[p] = j;
        }
    }
    __syncthreads();
    int m = sccnt;
    bool fits = (m <= 2048);
    int obase = socnt;

    for (int t = 0; t < need; t++) {
        unsigned long long last = s_last;
        unsigned long long best = ~0ull;
        if (fits) {
            for (int c = tid; c < m; c += 256) {
                int j = cand[c];
                unsigned long long key = ((unsigned long long)skey[j] << 32) | (unsigned)j;
                if (key > last && key < best) best = key;
            }
        } else {
            for (int j = tid; j < 4096; j += 256) {
                unsigned u = skey[j];
                if ((u & pmask) == prefix) {
                    unsigned long long key = ((unsigned long long)u << 32) | (unsigned)j;
                    if (key > last && key < best) best = key;
                }
            }
        }
#pragma unroll
        for (int off = 16; off; off >>= 1) {
            unsigned long long o = __shfl_down_sync(0xffffffffu, best, off);
            if (o < best) best = o;
        }
        if (lane == 0) wred[warp] = best;
        __syncthreads();
        if (tid == 0) {
            unsigned long long bb = wred[0];
#pragma unroll
            for (int w = 1; w < 8; w++) if (wred[w] < bb) bb = wred[w];
            orow[obase + t] = (int)(bb & 0xffffffffu);
            s_last = bb;
        }
        __syncthreads();
    }
}

// ---------------- weight pack ----------------
__global__ void wpack_k(const float* __restrict__ w, int C, int O, float* __restrict__ wp)
{
    int i = blockIdx.x * blockDim.x + threadIdx.x;
    if (i >= O * C) return;
    int o = i / C, c = i - o * C;
    float wa = w[o * 2 * C + c];
    wp[o * C + c] = wa;
    wp[(O + o) * C + c] = w[o * 2 * C + C + c] - wa;
}

// ---------------- edge gather + max + BN + leaky ----------------
__global__ void combine_k(const float* __restrict__ qp, int O,
                          const int* __restrict__ idx,
                          const float* __restrict__ sv, const float* __restrict__ bv,
                          float* __restrict__ out, int ldo)
{
    __shared__ int nb[20];
    int r = blockIdx.x;
    int base = (r >> 12) << 12;
    int tid = threadIdx.x;
    int ldq = 2 * O;
    if (tid < 20) nb[tid] = idx[(long)r * 20 + tid];
    __syncthreads();
    for (int o = tid; o < O; o += blockDim.x) {
        float m = -FLT_MAX;
#pragma unroll
        for (int kk = 0; kk < 20; kk++)
            m = fmaxf(m, qp[(long)(base + nb[kk]) * ldq + o]);
        float v = sv[o] * (m + qp[(long)r * ldq + O + o]) + bv[o];
        out[(long)r * ldo + o] = lrelu(v);
    }
}

// ---------------- global max over N (two-pass) ----------------
__global__ void gmax1_k(const float* __restrict__ emb, float* __restrict__ part)
{
    int b = blockIdx.x >> 4, sp = blockIdx.x & 15;
    int o = blockIdx.y * 256 + threadIdx.x;
    const float* e = emb + ((long)b * 4096 + (long)sp * 256) * 1024 + o;
    float m = -FLT_MAX;
    for (int n = 0; n < 256; n++) m = fmaxf(m, e[(long)n * 1024]);
    part[(long)blockIdx.x * 1024 + o] = m;
}
__global__ void gmax2_k(const float* __restrict__ part, float* __restrict__ glob)
{
    int b = blockIdx.x; int o = blockIdx.y * 256 + threadIdx.x;
    float m = -FLT_MAX;
    for (int sp = 0; sp < 16; sp++) m = fmaxf(m, part[(long)(b * 16 + sp) * 1024 + o]);
    glob[(long)b * 1024 + o] = m;
}

// ---------------- host ----------------
static void set_smem_attrs()
{
    cudaFuncSetAttribute(gemm_cp<0,0>, cudaFuncAttributeMaxDynamicSharedMemorySize, SMEM_DYN);
    cudaFuncSetAttribute(gemm_cp<1,0>, cudaFuncAttributeMaxDynamicSharedMemorySize, SMEM_DYN);
    cudaFuncSetAttribute(gemm_cp<2,1>, cudaFuncAttributeMaxDynamicSharedMemorySize, SMEM_DYN);
    cudaFuncSetAttribute(gemm_cp<3,0>, cudaFuncAttributeMaxDynamicSharedMemorySize, SMEM_DYN);
    cudaFuncSetAttribute(gemm_cp<4,0>, cudaFuncAttributeMaxDynamicSharedMemorySize, SMEM_DYN);
}

extern "C" void kernel_launch(void* const* d_in, const int* in_sizes, int n_in,
                              void* d_out, int out_size)
{
    (void)in_sizes; (void)n_in; (void)out_size;
    const float* xyz = (const float*)d_in[0];
    const float* w1 = (const float*)d_in[2];  const float* s1 = (const float*)d_in[3];  const float* b1 = (const float*)d_in[4];
    const float* w2 = (const float*)d_in[5];  const float* s2 = (const float*)d_in[6];  const float* b2 = (const float*)d_in[7];
    const float* w3 = (const float*)d_in[8];  const float* s3 = (const float*)d_in[9];  const float* b3 = (const float*)d_in[10];
    const float* w4 = (const float*)d_in[11]; const float* s4 = (const float*)d_in[12]; const float* b4 = (const float*)d_in[13];
    const float* wf = (const float*)d_in[14]; const float* sf = (const float*)d_in[15]; const float* bf = (const float*)d_in[16];
    const float* we = (const float*)d_in[17]; const float* se = (const float*)d_in[18]; const float* be = (const float*)d_in[19];
    const float* wh1 = (const float*)d_in[20]; const float* sh1 = (const float*)d_in[21]; const float* bh1 = (const float*)d_in[22];
    const float* wh2 = (const float*)d_in[23]; const float* sh2 = (const float*)d_in[24]; const float* bh2 = (const float*)d_in[25];
    const float* wh3 = (const float*)d_in[26]; const float* bh3 = (const float*)d_in[27];
    float* out = (float*)d_out;

    float *gd, *gcat, *gqp, *gx2, *glocal, *gemb, *gpart, *gglob, *ggh, *gh1, *gh2, *gwp;
    unsigned *gah, *gal, *gbh, *gbl;
    int *gidx;
    cudaGetSymbolAddress((void**)&gd, g_d);
    cudaGetSymbolAddress((void**)&gcat, g_cat);
    cudaGetSymbolAddress((void**)&gqp, g_qp);
    cudaGetSymbolAddress((void**)&gx2, g_x2);
    cudaGetSymbolAddress((void**)&gidx, g_idx);
    cudaGetSymbolAddress((void**)&glocal, g_local);
    cudaGetSymbolAddress((void**)&gemb, g_emb);
    cudaGetSymbolAddress((void**)&gpart, g_part);
    cudaGetSymbolAddress((void**)&gglob, g_glob);
    cudaGetSymbolAddress((void**)&ggh, g_gh);
    cudaGetSymbolAddress((void**)&gh1, g_h1);
    cudaGetSymbolAddress((void**)&gh2, g_h2);
    cudaGetSymbolAddress((void**)&gwp, g_wp);
    cudaGetSymbolAddress((void**)&gah, g_ah);
    cudaGetSymbolAddress((void**)&gal, g_al);
    cudaGetSymbolAddress((void**)&gbh, g_bh);
    cudaGetSymbolAddress((void**)&gbl, g_bl);

    set_smem_attrs();

    const int B = 4, N = 4096, M = B * N;

    // conv: src[rows x ld] (C cols) -> gah/gal or gbh/gbl padded [rowspad x K16]
    auto conv_act = [&](const float* src, int ld, int C, int K16) {
        conv_k<<<M, 256>>>(src, ld, M, C, K16, gah, gal);
    };
    auto conv_wt = [&](const float* src, int ld, int rows, int rowspad, int C, int K16) {
        conv_k<<<rowspad, 256>>>(src, ld, rows, C, K16, gbh, gbl);
    };

    auto edge_layer = [&](const float* X, int ldx, int C,
                          const float* w, const float* sv, const float* bv,
                          int O, float* outCol) {
        int K16 = (C + 15) & ~15;
        conv_act(X, ldx, C, K16);
        wpack_k<<<(O * C + 255) / 256, 256>>>(w, C, O, gwp);
        conv_wt(gwp, C, 2 * O, 2 * O, C, K16);
        sqnorm_k<<<M / 8, 256>>>(X, ldx, C, gx2);
        // symmetric distance GEMM (per-batch views of converted activations)
        {
            int T = N / 128;
            dim3 grid(T * (T + 1) / 2, 1, B);
            gemm_cp<2,1><<<grid, 256, SMEM_DYN>>>(
                gah, gal, K16, (long)N * K16,
                gah, gal, K16, (long)N * K16,
                gd, N, (long)N * N, N, K16, N, nullptr, nullptr, gx2, N);
        }
        topk_k<<<M, 256>>>(gd, gidx);
        // [q|p] = X * [w1 ; (w2-w1)]^T
        {
            dim3 grid((2 * O) / 128, M / 128, 1);
            gemm_cp<0,0><<<grid, 256, SMEM_DYN>>>(
                gah, gal, K16, 0, gbh, gbl, K16, 0,
                gqp, 2 * O, 0, M, K16, 2 * O, nullptr, nullptr, nullptr, 0);
        }
        combine_k<<<M, 128>>>(gqp, O, gidx, sv, bv, outCol, 512);
    };

    edge_layer(xyz,        3,   3,   w1, s1, b1, 64,  gcat + 0);
    edge_layer(gcat + 0,   512, 64,  w2, s2, b2, 64,  gcat + 64);
    edge_layer(gcat + 64,  512, 64,  w3, s3, b3, 128, gcat + 128);
    edge_layer(gcat + 128, 512, 128, w4, s4, b4, 256, gcat + 256);

    // x_local = leaky(cat * wf^T * sf + bf)
    conv_act(gcat, 512, 512, 512);
    conv_wt(wf, 512, 512, 512, 512, 512);
    { dim3 g(512 / 128, M / 128); gemm_cp<1,0><<<g, 256, SMEM_DYN>>>(
        gah, gal, 512, 0, gbh, gbl, 512, 0, glocal, 512, 0, M, 512, 512, sf, bf, nullptr, 0); }

    // x_emb = leaky(local * we^T * se + be)
    conv_act(glocal, 512, 512, 512);
    conv_wt(we, 512, 1024, 1024, 512, 512);
    { dim3 g(1024 / 128, M / 128); gemm_cp<1,0><<<g, 256, SMEM_DYN>>>(
        gah, gal, 512, 0, gbh, gbl, 512, 0, gemb, 1024, 0, M, 512, 1024, se, be, nullptr, 0); }

    { dim3 g1(64, 4); gmax1_k<<<g1, 256>>>(gemb, gpart); }
    { dim3 g2(4, 4);  gmax2_k<<<g2, 256>>>(gpart, gglob); }

    // G[b][o] = glob * wh1[:,512:]^T  (tiny: old scalar kernel)
    { dim3 g(2, 1); gemm_t<0><<<g, 256>>>(gglob, 1024, wh1 + 512, 1536, ggh, 256, B, 1024, 256); }

    // h1 = leaky(sh1*(local*wh1[:,:512]^T + G[b]) + bh1)   (gah still holds glocal)
    conv_wt(wh1, 1536, 256, 256, 512, 512);
    { dim3 g(256 / 128, M / 128); gemm_cp<3,0><<<g, 256, SMEM_DYN>>>(
        gah, gal, 512, 0, gbh, gbl, 512, 0, gh1, 256, 0, M, 512, 256, sh1, bh1, ggh, 256); }

    // h2 = leaky(h1*wh2^T * sh2 + bh2)
    conv_act(gh1, 256, 256, 256);
    conv_wt(wh2, 256, 256, 256, 256, 256);
    { dim3 g(256 / 128, M / 128); gemm_cp<1,0><<<g, 256, SMEM_DYN>>>(
        gah, gal, 256, 0, gbh, gbl, 256, 0, gh2, 256, 0, M, 256, 256, sh2, bh2, nullptr, 0); }

    // logits = h2*wh3^T + bh3   (wh3 rows padded 50 -> 128 with zeros)
    conv_act(gh2, 256, 256, 256);
    conv_wt(wh3, 256, 50, 128, 256, 256);
    { dim3 g(1, M / 128); gemm_cp<4,0><<<g, 256, SMEM_DYN>>>(
        gah, gal, 256, 0, gbh, gbl, 256, 0, out, 50, 0, M, 256, 50, nullptr, bh3, nullptr, 0); }
}

// round 9
// speedup vs baseline: 2.6334x; 1.1577x over previous
#include <cuda_runtime.h>
#include <cuda_bf16.h>
#include <cfloat>

#define LEAKF 0.2f
#define SPAD 20
#define PLANE (128 * SPAD)          // unsigned elems per smem plane
#define PLANEB (PLANE * 4)          // bytes
#define STAGEB (4 * PLANEB)         // bytes per stage (Ah,Al,Bh,Bl)
#define SMEM_DYN (2 * STAGEB)       // 81920 bytes

// ---------------- device scratch (no allocation allowed) ----------------
__device__ float g_d[4L * 4096 * 4096];   // 256 MB distance matrices
__device__ float g_cat[16384L * 512];
__device__ float g_qp[16384L * 512];
__device__ float g_x2[16384];
__device__ int   g_idx[16384L * 20];
__device__ float g_local[16384L * 512];
__device__ float g_emb[16384L * 1024];
__device__ float g_part[64L * 1024];
__device__ float g_glob[4L * 1024];
__device__ float g_gh[4L * 256];
__device__ float g_h1[16384L * 256];
__device__ float g_h2[16384L * 256];
__device__ float g_wp[512 * 128];
__device__ unsigned g_ah[16384L * 512];   // activation hi (tf32 bits), dense ld=K16
__device__ unsigned g_al[16384L * 512];   // activation lo
__device__ unsigned g_bh[1024L * 1536];   // weight hi
__device__ unsigned g_bl[1024L * 1536];   // weight lo

__device__ __forceinline__ float lrelu(float v) { return v > 0.f ? v : LEAKF * v; }

__device__ __forceinline__ unsigned f2tf32(float v) {
    unsigned r;
    asm("cvt.rna.tf32.f32 %0, %1;" : "=r"(r) : "f"(v));
    return r;
}

__device__ __forceinline__ void cpasync16(unsigned saddr, const void* g) {
    asm volatile("cp.async.ca.shared.global [%0], [%1], 16;" :: "r"(saddr), "l"(g));
}
__device__ __forceinline__ void cpcommit() { asm volatile("cp.async.commit_group;"); }
template<int N>
__device__ __forceinline__ void cpwait() { asm volatile("cp.async.wait_group %0;" :: "n"(N)); }

// ---------------- tf32 hi/lo pre-decomposition ----------------
__global__ void conv_k(const float* __restrict__ src, int ld, int rows, int C,
                       int K16, unsigned* __restrict__ oh, unsigned* __restrict__ ol)
{
    int r = blockIdx.x;
    for (int c = threadIdx.x; c < K16; c += blockDim.x) {
        float v = (r < rows && c < C) ? src[(long)r * ld + c] : 0.f;
        unsigned h = f2tf32(v);
        long i = (long)r * K16 + c;
        oh[i] = h;
        ol[i] = f2tf32(v - __uint_as_float(h));
    }
}

// ---------------- 128x128 3xTF32 MMA GEMM, cp.async double-buffered --------------
// MODE 0: Y = acc
// MODE 1: Y = leaky(acc*s[n] + b[n])
// MODE 2: Y = x2[m] + x2[n] - 2*acc  (SYM=1: upper-tri tiles, mirrored writes)
// MODE 3: Y = leaky(s[n]*(acc + aux[(m>>12)*auxS + n]) + b[n])
// MODE 4: Y = acc + b[n]
template<int MODE, int SYM>
__global__ __launch_bounds__(256, 2)
void gemm_cp(const unsigned* __restrict__ Agh, const unsigned* __restrict__ Agl,
             int lda, long abs_,
             const unsigned* __restrict__ Bgh, const unsigned* __restrict__ Bgl,
             int ldb, long bbs,
             float* __restrict__ Y, int ldy, long ybs,
             int M, int K16, int NO,
             const float* __restrict__ sv, const float* __restrict__ bv,
             const float* __restrict__ aux, int auxS)
{
    extern __shared__ unsigned smd[];
    unsigned sb32 = (unsigned)__cvta_generic_to_shared(smd);

    int z = blockIdx.z;
    const unsigned* Ah_g = Agh + (long)z * abs_;
    const unsigned* Al_g = Agl + (long)z * abs_;
    const unsigned* Bh_g = Bgh + (long)z * bbs;
    const unsigned* Bl_g = Bgl + (long)z * bbs;
    float* Yb = Y + (long)z * ybs;

    int row0, col0;
    if (SYM) {
        int T = (M + 127) >> 7;
        int t = blockIdx.x;
        float ff = (float)(2 * T + 1);
        int bi = (int)((ff - sqrtf(ff * ff - 8.f * (float)t)) * 0.5f);
        while ((bi + 1) * T - ((bi + 1) * bi) / 2 <= t) bi++;
        while (bi * T - (bi * (bi - 1)) / 2 > t) bi--;
        int bj = bi + (t - (bi * T - (bi * (bi - 1)) / 2));
        row0 = bi << 7;
        col0 = bj << 7;
    } else {
        row0 = blockIdx.y * 128;
        col0 = blockIdx.x * 128;
    }

    int tid = threadIdx.x;
    int lane = tid & 31, wid = tid >> 5;
    int wm = wid & 3, wn = wid >> 2;
    int grp = lane >> 2, tig = lane & 3;

    float acc[2][8][4];
#pragma unroll
    for (int h = 0; h < 2; h++)
#pragma unroll
        for (int j = 0; j < 8; j++)
#pragma unroll
            for (int c = 0; c < 4; c++) acc[h][j][c] = 0.f;

    int nch = K16 >> 4;

    auto load_stage = [&](int stage, int k0) {
        unsigned base = sb32 + stage * STAGEB;
#pragma unroll
        for (int v = 0; v < 2; v++) {
            int vec = tid + v * 256;
            int row = vec >> 2, seg = (vec & 3) * 4;
            unsigned soff = (unsigned)(row * SPAD + seg) * 4u;
            long goa = (long)(row0 + row) * lda + k0 + seg;
            long gob = (long)(col0 + row) * ldb + k0 + seg;
            cpasync16(base + soff,              Ah_g + goa);
            cpasync16(base + PLANEB + soff,     Al_g + goa);
            cpasync16(base + 2 * PLANEB + soff, Bh_g + gob);
            cpasync16(base + 3 * PLANEB + soff, Bl_g + gob);
        }
        cpcommit();
    };

    load_stage(0, 0);

    for (int ch = 0; ch < nch; ch++) {
        int cur = ch & 1;
        if (ch + 1 < nch) load_stage(cur ^ 1, (ch + 1) << 4);
        if (ch + 1 < nch) cpwait<1>(); else cpwait<0>();
        __syncthreads();

        const unsigned* Ah = smd + cur * 4 * PLANE;
        const unsigned* Al = Ah + PLANE;
        const unsigned* Bh = Al + PLANE;
        const unsigned* Bl = Bh + PLANE;

#pragma unroll
        for (int ks = 0; ks < 16; ks += 8) {
            unsigned ah[2][4], al[2][4];
#pragma unroll
            for (int h = 0; h < 2; h++) {
                int mb = wm * 32 + h * 16;
                int i0 = (mb + grp) * SPAD + ks + tig;
                int i1 = (mb + grp + 8) * SPAD + ks + tig;
                ah[h][0] = Ah[i0]; ah[h][1] = Ah[i1];
                ah[h][2] = Ah[i0 + 4]; ah[h][3] = Ah[i1 + 4];
                al[h][0] = Al[i0]; al[h][1] = Al[i1];
                al[h][2] = Al[i0 + 4]; al[h][3] = Al[i1 + 4];
            }
#pragma unroll
            for (int j = 0; j < 8; j++) {
                int nb = wn * 64 + j * 8;
                int ib = (nb + grp) * SPAD + ks + tig;
                unsigned bh0 = Bh[ib], bh1 = Bh[ib + 4];
                unsigned bl0 = Bl[ib], bl1 = Bl[ib + 4];
#pragma unroll
                for (int h = 0; h < 2; h++) {
                    asm volatile(
                        "mma.sync.aligned.m16n8k8.row.col.f32.tf32.tf32.f32 "
                        "{%0,%1,%2,%3}, {%4,%5,%6,%7}, {%8,%9}, {%0,%1,%2,%3};"
                        : "+f"(acc[h][j][0]), "+f"(acc[h][j][1]),
                          "+f"(acc[h][j][2]), "+f"(acc[h][j][3])
                        : "r"(al[h][0]), "r"(al[h][1]), "r"(al[h][2]), "r"(al[h][3]),
                          "r"(bh0), "r"(bh1));
                    asm volatile(
                        "mma.sync.aligned.m16n8k8.row.col.f32.tf32.tf32.f32 "
                        "{%0,%1,%2,%3}, {%4,%5,%6,%7}, {%8,%9}, {%0,%1,%2,%3};"
                        : "+f"(acc[h][j][0]), "+f"(acc[h][j][1]),
                          "+f"(acc[h][j][2]), "+f"(acc[h][j][3])
                        : "r"(ah[h][0]), "r"(ah[h][1]), "r"(ah[h][2]), "r"(ah[h][3]),
                          "r"(bl0), "r"(bl1));
                    asm volatile(
                        "mma.sync.aligned.m16n8k8.row.col.f32.tf32.tf32.f32 "
                        "{%0,%1,%2,%3}, {%4,%5,%6,%7}, {%8,%9}, {%0,%1,%2,%3};"
                        : "+f"(acc[h][j][0]), "+f"(acc[h][j][1]),
                          "+f"(acc[h][j][2]), "+f"(acc[h][j][3])
                        : "r"(ah[h][0]), "r"(ah[h][1]), "r"(ah[h][2]), "r"(ah[h][3]),
                          "r"(bh0), "r"(bh1));
                }
            }
        }
        __syncthreads();
    }

#pragma unroll
    for (int h = 0; h < 2; h++) {
        int r0 = row0 + wm * 32 + h * 16 + grp;
#pragma unroll
        for (int j = 0; j < 8; j++) {
            int cb = col0 + wn * 64 + j * 8 + 2 * tig;
#pragma unroll
            for (int half = 0; half < 2; half++) {
                int gm = r0 + half * 8;
                if (gm >= M) continue;
#pragma unroll
                for (int cc = 0; cc < 2; cc++) {
                    int gn = cb + cc;
                    if (gn >= NO) continue;
                    float v = acc[h][j][half * 2 + cc];
                    if (MODE == 1) v = lrelu(v * sv[gn] + bv[gn]);
                    else if (MODE == 2) {
                        const float* x2 = aux + (long)z * auxS;
                        v = x2[gm] + x2[gn] - 2.f * v;
                    } else if (MODE == 3) {
                        int bb = gm >> 12;
                        v = lrelu(sv[gn] * (v + aux[bb * auxS + gn]) + bv[gn]);
                    } else if (MODE == 4) v = v + bv[gn];
                    Yb[(long)gm * ldy + gn] = v;
                    if (SYM) Yb[(long)gn * ldy + gm] = v;
                }
            }
        }
    }
}

// ---------------- old scalar-load 3xTF32 GEMM (tiny 4x256 GEMM only) ------
template<int MODE>
__global__ __launch_bounds__(256, 2)
void gemm_t(const float* __restrict__ X, int ldx,
            const float* __restrict__ W, int ldw,
            float* __restrict__ Y, int ldy,
            int M, int K, int NO)
{
    __shared__ unsigned Ah[128 * SPAD];
    __shared__ unsigned Bh[128 * SPAD];
    __shared__ unsigned Al[128 * SPAD];
    __shared__ unsigned Bl[128 * SPAD];

    int row0 = blockIdx.y * 128;
    int col0 = blockIdx.x * 128;
    int tid = threadIdx.x;
    int lane = tid & 31, wid = tid >> 5;
    int wm = wid & 3, wn = wid >> 2;
    int grp = lane >> 2, tig = lane & 3;

    float acc[2][8][4];
#pragma unroll
    for (int h = 0; h < 2; h++)
#pragma unroll
        for (int j = 0; j < 8; j++)
#pragma unroll
            for (int c = 0; c < 4; c++) acc[h][j][c] = 0.f;

    int nchunks = (K + 15) >> 4;
    for (int ch = 0; ch < nchunks; ch++) {
        int k0 = ch << 4;
#pragma unroll
        for (int i = 0; i < 8; i++) {
            int li = tid * 8 + i;
            int rrow = li >> 4, rcol = li & 15;
            int gk = k0 + rcol;
            int gm = row0 + rrow;
            float va = (gm < M && gk < K) ? X[(long)gm * ldx + gk] : 0.f;
            unsigned vah = f2tf32(va);
            Ah[rrow * SPAD + rcol] = vah;
            Al[rrow * SPAD + rcol] = f2tf32(va - __uint_as_float(vah));
            int gn = col0 + rrow;
            float vb = (gn < NO && gk < K) ? W[(long)gn * ldw + gk] : 0.f;
            unsigned vbh = f2tf32(vb);
            Bh[rrow * SPAD + rcol] = vbh;
            Bl[rrow * SPAD + rcol] = f2tf32(vb - __uint_as_float(vbh));
        }
        __syncthreads();
#pragma unroll
        for (int ks = 0; ks < 16; ks += 8) {
            unsigned ah[2][4], al[2][4];
#pragma unroll
            for (int h = 0; h < 2; h++) {
                int mb = wm * 32 + h * 16;
                int i0 = (mb + grp) * SPAD + ks + tig;
                int i1 = (mb + grp + 8) * SPAD + ks + tig;
                ah[h][0] = Ah[i0]; ah[h][1] = Ah[i1];
                ah[h][2] = Ah[i0 + 4]; ah[h][3] = Ah[i1 + 4];
                al[h][0] = Al[i0]; al[h][1] = Al[i1];
                al[h][2] = Al[i0 + 4]; al[h][3] = Al[i1 + 4];
            }
#pragma unroll
            for (int j = 0; j < 8; j++) {
                int nb = wn * 64 + j * 8;
                int ib = (nb + grp) * SPAD + ks + tig;
                unsigned bh0 = Bh[ib], bh1 = Bh[ib + 4];
                unsigned bl0 = Bl[ib], bl1 = Bl[ib + 4];
#pragma unroll
                for (int h = 0; h < 2; h++) {
                    asm volatile(
                        "mma.sync.aligned.m16n8k8.row.col.f32.tf32.tf32.f32 "
                        "{%0,%1,%2,%3}, {%4,%5,%6,%7}, {%8,%9}, {%0,%1,%2,%3};"
                        : "+f"(acc[h][j][0]), "+f"(acc[h][j][1]),
                          "+f"(acc[h][j][2]), "+f"(acc[h][j][3])
                        : "r"(al[h][0]), "r"(al[h][1]), "r"(al[h][2]), "r"(al[h][3]),
                          "r"(bh0), "r"(bh1));
                    asm volatile(
                        "mma.sync.aligned.m16n8k8.row.col.f32.tf32.tf32.f32 "
                        "{%0,%1,%2,%3}, {%4,%5,%6,%7}, {%8,%9}, {%0,%1,%2,%3};"
                        : "+f"(acc[h][j][0]), "+f"(acc[h][j][1]),
                          "+f"(acc[h][j][2]), "+f"(acc[h][j][3])
                        : "r"(ah[h][0]), "r"(ah[h][1]), "r"(ah[h][2]), "r"(ah[h][3]),
                          "r"(bl0), "r"(bl1));
                    asm volatile(
                        "mma.sync.aligned.m16n8k8.row.col.f32.tf32.tf32.f32 "
                        "{%0,%1,%2,%3}, {%4,%5,%6,%7}, {%8,%9}, {%0,%1,%2,%3};"
                        : "+f"(acc[h][j][0]), "+f"(acc[h][j][1]),
                          "+f"(acc[h][j][2]), "+f"(acc[h][j][3])
                        : "r"(ah[h][0]), "r"(ah[h][1]), "r"(ah[h][2]), "r"(ah[h][3]),
                          "r"(bh0), "r"(bh1));
                }
            }
        }
        __syncthreads();
    }
#pragma unroll
    for (int h = 0; h < 2; h++) {
        int r0 = row0 + wm * 32 + h * 16 + grp;
#pragma unroll
        for (int j = 0; j < 8; j++) {
            int cb = col0 + wn * 64 + j * 8 + 2 * tig;
#pragma unroll
            for (int half = 0; half < 2; half++) {
                int gm = r0 + half * 8;
                if (gm >= M) continue;
#pragma unroll
                for (int cc = 0; cc < 2; cc++) {
                    int gn = cb + cc;
                    if (gn >= NO) continue;
                    Y[(long)gm * ldy + gn] = acc[h][j][half * 2 + cc];
                }
            }
        }
    }
}

// ---------------- squared norms (warp per row) ----------------
__global__ void sqnorm_k(const float* __restrict__ X, int ldx, int C, float* __restrict__ x2)
{
    int warp = (blockIdx.x * blockDim.x + threadIdx.x) >> 5;
    int lane = threadIdx.x & 31;
    if (warp >= 16384) return;
    const float* xr = X + (long)warp * ldx;
    float s = 0.f;
    for (int c = lane; c < C; c += 32) { float v = xr[c]; s = fmaf(v, v, s); }
#pragma unroll
    for (int off = 16; off; off >>= 1) s += __shfl_down_sync(0xffffffffu, s, off);
    if (lane == 0) x2[warp] = s;
}

// ---------------- top-20 smallest: single-pass 2048-bin radix select ----------------
// One histogram scan + warp-shuffle scan over 2048 bins + one emission scan +
// exact finish on the (tiny) boundary-bin candidate set. Output order arbitrary
// (consumer is a max over the neighbor set); set is exact with (key,idx) ties.
__global__ __launch_bounds__(256) void topk_k(const float* __restrict__ D, int* __restrict__ idx)
{
    __shared__ unsigned skey[4096];
    __shared__ int hist[2048];
    __shared__ int cand[4096];
    __shared__ int wsum[8];
    __shared__ int sb, sexcl, socnt, sccnt;
    __shared__ unsigned long long wred[8];
    __shared__ unsigned long long s_last;

    long r = blockIdx.x;
    const float4* drow = (const float4*)(D + r * 4096);
    int* orow = idx + r * 20;
    int tid = threadIdx.x;
    int lane = tid & 31, warp = tid >> 5;

#pragma unroll
    for (int i = 0; i < 8; i++) hist[tid + i * 256] = 0;
    if (tid == 0) { socnt = 0; sccnt = 0; s_last = 0ull; }
    __syncthreads();

    // scan 1: load, convert, histogram (top 11 bits)
#pragma unroll
    for (int v = 0; v < 4; v++) {
        int j4 = tid + v * 256;
        float4 d4 = drow[j4];
        unsigned k0 = __float_as_uint(fmaxf(d4.x, 0.f));
        unsigned k1 = __float_as_uint(fmaxf(d4.y, 0.f));
        unsigned k2 = __float_as_uint(fmaxf(d4.z, 0.f));
        unsigned k3 = __float_as_uint(fmaxf(d4.w, 0.f));
        skey[j4 * 4 + 0] = k0; skey[j4 * 4 + 1] = k1;
        skey[j4 * 4 + 2] = k2; skey[j4 * 4 + 3] = k3;
        atomicAdd(&hist[k0 >> 21], 1);
        atomicAdd(&hist[k1 >> 21], 1);
        atomicAdd(&hist[k2 >> 21], 1);
        atomicAdd(&hist[k3 >> 21], 1);
    }
    __syncthreads();

    // per-thread sum of its 8 contiguous bins, then block scan of 256 partials
    int csum[8];
    int tot = 0;
#pragma unroll
    for (int i = 0; i < 8; i++) { tot += hist[tid * 8 + i]; csum[i] = tot; }
    // warp inclusive scan
    int sc = tot;
#pragma unroll
    for (int off = 1; off < 32; off <<= 1) {
        int t = __shfl_up_sync(0xffffffffu, sc, off);
        if (lane >= off) sc += t;
    }
    if (lane == 31) wsum[warp] = sc;
    __syncthreads();
    if (tid < 8) {
        int w = wsum[tid];
#pragma unroll
        for (int off = 1; off < 8; off <<= 1) {
            int t = __shfl_up_sync(0xffu, w, off);
            if (tid >= off) w += t;
        }
        wsum[tid] = w;
    }
    __syncthreads();
    int base = sc - tot + (warp ? wsum[warp - 1] : 0);   // exclusive prefix of this thread's bins

    // locate boundary bin (excl < 20 <= incl)
    if (base < 20 && base + tot >= 20) {
#pragma unroll
        for (int i = 0; i < 8; i++) {
            int incl = base + csum[i];
            int excl = incl - hist[tid * 8 + i];
            if (excl < 20 && incl >= 20) { sb = tid * 8 + i; sexcl = excl; }
        }
    }
    __syncthreads();
    unsigned b = (unsigned)sb;
    int need = 20 - sexcl;

    // scan 2: emit winners (bin < b), compact boundary candidates (bin == b)
    for (int j = tid; j < 4096; j += 256) {
        unsigned bin = skey[j] >> 21;
        if (bin < b) {
            int p = atomicAdd(&socnt, 1);
            orow[p] = j;
        } else if (bin == b) {
            int p = atomicAdd(&sccnt, 1);
            cand[p] = j;
        }
    }
    __syncthreads();
    int m = sccnt;
    int obase = socnt;

    // exact finish on candidates (usually m is tiny)
    for (int t = 0; t < need; t++) {
        unsigned long long last = s_last;
        unsigned long long best = ~0ull;
        for (int c = tid; c < m; c += 256) {
            int j = cand[c];
            unsigned long long key = ((unsigned long long)skey[j] << 32) | (unsigned)j;
            if (key > last && key < best) best = key;
        }
#pragma unroll
        for (int off = 16; off; off >>= 1) {
            unsigned long long o = __shfl_down_sync(0xffffffffu, best, off);
            if (o < best) best = o;
        }
        if (lane == 0) wred[warp] = best;
        __syncthreads();
        if (tid == 0) {
            unsigned long long bb = wred[0];
#pragma unroll
            for (int w = 1; w < 8; w++) if (wred[w] < bb) bb = wred[w];
            orow[obase + t] = (int)(bb & 0xffffffffu);
            s_last = bb;
        }
        __syncthreads();
    }
}

// ---------------- weight pack ----------------
__global__ void wpack_k(const float* __restrict__ w, int C, int O, float* __restrict__ wp)
{
    int i = blockIdx.x * blockDim.x + threadIdx.x;
    if (i >= O * C) return;
    int o = i / C, c = i - o * C;
    float wa = w[o * 2 * C + c];
    wp[o * C + c] = wa;
    wp[(O + o) * C + c] = w[o * 2 * C + C + c] - wa;
}

// ---------------- edge gather + max + BN + leaky ----------------
__global__ void combine_k(const float* __restrict__ qp, int O,
                          const int* __restrict__ idx,
                          const float* __restrict__ sv, const float* __restrict__ bv,
                          float* __restrict__ out, int ldo)
{
    __shared__ int nb[20];
    int r = blockIdx.x;
    int base = (r >> 12) << 12;
    int tid = threadIdx.x;
    int ldq = 2 * O;
    if (tid < 20) nb[tid] = idx[(long)r * 20 + tid];
    __syncthreads();
    for (int o = tid; o < O; o += blockDim.x) {
        float m = -FLT_MAX;
#pragma unroll
        for (int kk = 0; kk < 20; kk++)
            m = fmaxf(m, qp[(long)(base + nb[kk]) * ldq + o]);
        float v = sv[o] * (m + qp[(long)r * ldq + O + o]) + bv[o];
        out[(long)r * ldo + o] = lrelu(v);
    }
}

// ---------------- global max over N (two-pass) ----------------
__global__ void gmax1_k(const float* __restrict__ emb, float* __restrict__ part)
{
    int b = blockIdx.x >> 4, sp = blockIdx.x & 15;
    int o = blockIdx.y * 256 + threadIdx.x;
    const float* e = emb + ((long)b * 4096 + (long)sp * 256) * 1024 + o;
    float m = -FLT_MAX;
    for (int n = 0; n < 256; n++) m = fmaxf(m, e[(long)n * 1024]);
    part[(long)blockIdx.x * 1024 + o] = m;
}
__global__ void gmax2_k(const float* __restrict__ part, float* __restrict__ glob)
{
    int b = blockIdx.x; int o = blockIdx.y * 256 + threadIdx.x;
    float m = -FLT_MAX;
    for (int sp = 0; sp < 16; sp++) m = fmaxf(m, part[(long)(b * 16 + sp) * 1024 + o]);
    glob[(long)b * 1024 + o] = m;
}

// ---------------- host ----------------
static void set_smem_attrs()
{
    cudaFuncSetAttribute(gemm_cp<0,0>, cudaFuncAttributeMaxDynamicSharedMemorySize, SMEM_DYN);
    cudaFuncSetAttribute(gemm_cp<1,0>, cudaFuncAttributeMaxDynamicSharedMemorySize, SMEM_DYN);
    cudaFuncSetAttribute(gemm_cp<2,1>, cudaFuncAttributeMaxDynamicSharedMemorySize, SMEM_DYN);
    cudaFuncSetAttribute(gemm_cp<3,0>, cudaFuncAttributeMaxDynamicSharedMemorySize, SMEM_DYN);
    cudaFuncSetAttribute(gemm_cp<4,0>, cudaFuncAttributeMaxDynamicSharedMemorySize, SMEM_DYN);
}

extern "C" void kernel_launch(void* const* d_in, const int* in_sizes, int n_in,
                              void* d_out, int out_size)
{
    (void)in_sizes; (void)n_in; (void)out_size;
    const float* xyz = (const float*)d_in[0];
    const float* w1 = (const float*)d_in[2];  const float* s1 = (const float*)d_in[3];  const float* b1 = (const float*)d_in[4];
    const float* w2 = (const float*)d_in[5];  const float* s2 = (const float*)d_in[6];  const float* b2 = (const float*)d_in[7];
    const float* w3 = (const float*)d_in[8];  const float* s3 = (const float*)d_in[9];  const float* b3 = (const float*)d_in[10];
    const float* w4 = (const float*)d_in[11]; const float* s4 = (const float*)d_in[12]; const float* b4 = (const float*)d_in[13];
    const float* wf = (const float*)d_in[14]; const float* sf = (const float*)d_in[15]; const float* bf = (const float*)d_in[16];
    const float* we = (const float*)d_in[17]; const float* se = (const float*)d_in[18]; const float* be = (const float*)d_in[19];
    const float* wh1 = (const float*)d_in[20]; const float* sh1 = (const float*)d_in[21]; const float* bh1 = (const float*)d_in[22];
    const float* wh2 = (const float*)d_in[23]; const float* sh2 = (const float*)d_in[24]; const float* bh2 = (const float*)d_in[25];
    const float* wh3 = (const float*)d_in[26]; const float* bh3 = (const float*)d_in[27];
    float* out = (float*)d_out;

    float *gd, *gcat, *gqp, *gx2, *glocal, *gemb, *gpart, *gglob, *ggh, *gh1, *gh2, *gwp;
    unsigned *gah, *gal, *gbh, *gbl;
    int *gidx;
    cudaGetSymbolAddress((void**)&gd, g_d);
    cudaGetSymbolAddress((void**)&gcat, g_cat);
    cudaGetSymbolAddress((void**)&gqp, g_qp);
    cudaGetSymbolAddress((void**)&gx2, g_x2);
    cudaGetSymbolAddress((void**)&gidx, g_idx);
    cudaGetSymbolAddress((void**)&glocal, g_local);
    cudaGetSymbolAddress((void**)&gemb, g_emb);
    cudaGetSymbolAddress((void**)&gpart, g_part);
    cudaGetSymbolAddress((void**)&gglob, g_glob);
    cudaGetSymbolAddress((void**)&ggh, g_gh);
    cudaGetSymbolAddress((void**)&gh1, g_h1);
    cudaGetSymbolAddress((void**)&gh2, g_h2);
    cudaGetSymbolAddress((void**)&gwp, g_wp);
    cudaGetSymbolAddress((void**)&gah, g_ah);
    cudaGetSymbolAddress((void**)&gal, g_al);
    cudaGetSymbolAddress((void**)&gbh, g_bh);
    cudaGetSymbolAddress((void**)&gbl, g_bl);

    set_smem_attrs();

    const int B = 4, N = 4096, M = B * N;

    auto conv_act = [&](const float* src, int ld, int C, int K16) {
        conv_k<<<M, 256>>>(src, ld, M, C, K16, gah, gal);
    };
    auto conv_wt = [&](const float* src, int ld, int rows, int rowspad, int C, int K16) {
        conv_k<<<rowspad, 256>>>(src, ld, rows, C, K16, gbh, gbl);
    };

    auto edge_layer = [&](const float* X, int ldx, int C,
                          const float* w, const float* sv, const float* bv,
                          int O, float* outCol) {
        int K16 = (C + 15) & ~15;
        conv_act(X, ldx, C, K16);
        wpack_k<<<(O * C + 255) / 256, 256>>>(w, C, O, gwp);
        conv_wt(gwp, C, 2 * O, 2 * O, C, K16);
        sqnorm_k<<<M / 8, 256>>>(X, ldx, C, gx2);
        {
            int T = N / 128;
            dim3 grid(T * (T + 1) / 2, 1, B);
            gemm_cp<2,1><<<grid, 256, SMEM_DYN>>>(
                gah, gal, K16, (long)N * K16,
                gah, gal, K16, (long)N * K16,
                gd, N, (long)N * N, N, K16, N, nullptr, nullptr, gx2, N);
        }
        topk_k<<<M, 256>>>(gd, gidx);
        {
            dim3 grid((2 * O) / 128, M / 128, 1);
            gemm_cp<0,0><<<grid, 256, SMEM_DYN>>>(
                gah, gal, K16, 0, gbh, gbl, K16, 0,
                gqp, 2 * O, 0, M, K16, 2 * O, nullptr, nullptr, nullptr, 0);
        }
        combine_k<<<M, 128>>>(gqp, O, gidx, sv, bv, outCol, 512);
    };

    edge_layer(xyz,        3,   3,   w1, s1, b1, 64,  gcat + 0);
    edge_layer(gcat + 0,   512, 64,  w2, s2, b2, 64,  gcat + 64);
    edge_layer(gcat + 64,  512, 64,  w3, s3, b3, 128, gcat + 128);
    edge_layer(gcat + 128, 512, 128, w4, s4, b4, 256, gcat + 256);

    conv_act(gcat, 512, 512, 512);
    conv_wt(wf, 512, 512, 512, 512, 512);
    { dim3 g(512 / 128, M / 128); gemm_cp<1,0><<<g, 256, SMEM_DYN>>>(
        gah, gal, 512, 0, gbh, gbl, 512, 0, glocal, 512, 0, M, 512, 512, sf, bf, nullptr, 0); }

    conv_act(glocal, 512, 512, 512);
    conv_wt(we, 512, 1024, 1024, 512, 512);
    { dim3 g(1024 / 128, M / 128); gemm_cp<1,0><<<g, 256, SMEM_DYN>>>(
        gah, gal, 512, 0, gbh, gbl, 512, 0, gemb, 1024, 0, M, 512, 1024, se, be, nullptr, 0); }

    { dim3 g1(64, 4); gmax1_k<<<g1, 256>>>(gemb, gpart); }
    { dim3 g2(4, 4);  gmax2_k<<<g2, 256>>>(gpart, gglob); }

    { dim3 g(2, 1); gemm_t<0><<<g, 256>>>(gglob, 1024, wh1 + 512, 1536, ggh, 256, B, 1024, 256); }

    conv_wt(wh1, 1536, 256, 256, 512, 512);
    { dim3 g(256 / 128, M / 128); gemm_cp<3,0><<<g, 256, SMEM_DYN>>>(
        gah, gal, 512, 0, gbh, gbl, 512, 0, gh1, 256, 0, M, 512, 256, sh1, bh1, ggh, 256); }

    conv_act(gh1, 256, 256, 256);
    conv_wt(wh2, 256, 256, 256, 256, 256);
    { dim3 g(256 / 128, M / 128); gemm_cp<1,0><<<g, 256, SMEM_DYN>>>(
        gah, gal, 256, 0, gbh, gbl, 256, 0, gh2, 256, 0, M, 256, 256, sh2, bh2, nullptr, 0); }

    conv_act(gh2, 256, 256, 256);
    conv_wt(wh3, 256, 50, 128, 256, 256);
    { dim3 g(1, M / 128); gemm_cp<4,0><<<g, 256, SMEM_DYN>>>(
        gah, gal, 256, 0, gbh, gbl, 256, 0, out, 50, 0, M, 256, 50, nullptr, bh3, nullptr, 0); }
}